// round 12
// baseline (speedup 1.0000x reference)
#include <cuda_runtime.h>
#include <cuda_fp16.h>
#include <cstdint>

// Problem constants
#define B_  2
#define L_  4096
#define HS_ 2048
#define NH_ 16
#define HD_ 128
#define FD_ 256
#define NROWS (B_*L_)            // 8192
#define NTOK  (B_*L_*NH_)        // 131072
#define BH_   (B_*NH_)           // 32

// Scratch layout (float units)
#define OFF_XH    ((size_t)0)                        // 8388608
#define OFF_QKV   ((size_t)8388608)                  // q|k|v each 8388608
#define OFF_TMPH  ((size_t)33554432)                 // 33554432 (262144x256 half)
#define OFF_QFH   ((size_t)67108864)                 // 16777216
#define OFF_KFH   ((size_t)83886080)                 // 16777216
#define OFF_KVP   ((size_t)100663296)                // 8388608
#define OFF_KVT   ((size_t)109051904)                // 524288
#define OFF_KSUM  ((size_t)109576192)                // 8192
#define OFF_DEN   ((size_t)109584384)                // 131072
#define OFF_ATTNH ((size_t)109715456)                // 8388608
#define OFF_WQKVT ((size_t)118104064)                // 6291456 (6144x2048 half)
#define OFF_WOT   ((size_t)124395520)                // 2097152
#define OFF_WF1T  ((size_t)126492672)                // 16384
#define OFF_WF2T  ((size_t)126509056)                // 32768
#define OFF_BQKV  ((size_t)126541824)                // 6144
#define SCRATCH_TOTAL ((size_t)126548992)

__device__ float g_scratch[SCRATCH_TOTAL];

// ---------------------------------------------------------------------------
// Helpers
// ---------------------------------------------------------------------------
__device__ __forceinline__ uint32_t smem_u32(const void* p) {
    uint32_t a;
    asm("{ .reg .u64 t; cvta.to.shared.u64 t, %1; cvt.u32.u64 %0, t; }"
        : "=r"(a) : "l"(p));
    return a;
}

#define CP_ASYNC16(saddr, gaddr) \
    asm volatile("cp.async.cg.shared.global [%0], [%1], 16;" \
                 :: "r"(saddr), "l"(gaddr))
#define CP_COMMIT() asm volatile("cp.async.commit_group;")

#define LDSM4(r, addr) \
    asm volatile("ldmatrix.sync.aligned.m8n8.x4.shared.b16 {%0,%1,%2,%3}, [%4];" \
                 : "=r"((r)[0]), "=r"((r)[1]), "=r"((r)[2]), "=r"((r)[3]) \
                 : "r"(addr))

#define LDSM4T(r, addr) \
    asm volatile("ldmatrix.sync.aligned.m8n8.x4.trans.shared.b16 {%0,%1,%2,%3}, [%4];" \
                 : "=r"((r)[0]), "=r"((r)[1]), "=r"((r)[2]), "=r"((r)[3]) \
                 : "r"(addr))

__device__ __forceinline__ void mma_f16(float* d, const uint32_t* a,
                                        uint32_t b0, uint32_t b1) {
    asm volatile(
        "mma.sync.aligned.m16n8k16.row.col.f32.f16.f16.f32 "
        "{%0,%1,%2,%3}, {%4,%5,%6,%7}, {%8,%9}, {%0,%1,%2,%3};"
        : "+f"(d[0]), "+f"(d[1]), "+f"(d[2]), "+f"(d[3])
        : "r"(a[0]), "r"(a[1]), "r"(a[2]), "r"(a[3]), "r"(b0), "r"(b1));
}

#define HROW_B   80

// ---------------------------------------------------------------------------
// gemm256: C = A[M,K]@BT[N,K]^T + bias. CTA 256x128, 8 warps 64x64 each,
// 4-stage cp.async. qkv_split: route output columns into 3 [NROWS,HS] bufs.
// ---------------------------------------------------------------------------
#define G2_ABYTES (256 * HROW_B)             // 20480
#define G2_BBYTES (128 * HROW_B)             // 10240
#define G2_STAGE  (G2_ABYTES + G2_BBYTES)    // 30720
#define G2_SMEM   (4 * G2_STAGE)             // 122880

__global__ __launch_bounds__(256, 1) void gemm256_kernel(
    const __half* __restrict__ A, const __half* __restrict__ BT,
    const float* __restrict__ bias, void* __restrict__ Cout,
    int M, int N, int K, int relu, int out_half, int qkv_split)
{
    extern __shared__ char smraw[];
    const uint32_t sbase = smem_u32(smraw);
    const int tid = threadIdx.x;
    const int wid = tid >> 5, lane = tid & 31;
    const int wm = wid & 3, wn = wid >> 2;       // 4 (M) x 2 (N)
    const int gid = lane >> 2, tig = lane & 3;
    const int n0 = blockIdx.x * 128, m0 = blockIdx.y * 256;

    float acc[4][8][4];
    #pragma unroll
    for (int mi = 0; mi < 4; mi++)
        #pragma unroll
        for (int ni = 0; ni < 8; ni++)
            #pragma unroll
            for (int j = 0; j < 4; j++) acc[mi][ni][j] = 0.f;

    const int nchunk = K >> 5;

    auto issue_chunk = [&](int c, int slot) {
        const __half* Ag = A + (size_t)m0 * K + c * 32;
        const __half* Bg = BT + (size_t)n0 * K + c * 32;
        const uint32_t sA = sbase + (uint32_t)slot * G2_STAGE;
        const uint32_t sB = sA + G2_ABYTES;
        #pragma unroll
        for (int r = 0; r < 4; r++) {
            const int idx = tid + 256 * r;       // 1024: 256 rows x 4 segs
            const int row = idx >> 2, seg = idx & 3;
            CP_ASYNC16(sA + (uint32_t)(row * HROW_B + seg * 16),
                       Ag + (size_t)row * K + seg * 8);
        }
        #pragma unroll
        for (int r = 0; r < 2; r++) {
            const int idx = tid + 256 * r;       // 512: 128 rows x 4 segs
            const int row = idx >> 2, seg = idx & 3;
            CP_ASYNC16(sB + (uint32_t)(row * HROW_B + seg * 16),
                       Bg + (size_t)row * K + seg * 8);
        }
    };

    #pragma unroll
    for (int p = 0; p < 3; p++) {
        if (p < nchunk) issue_chunk(p, p);
        CP_COMMIT();
    }

    const int l15 = lane & 15;
    const int koff = (lane >> 4) * 16;

    for (int c = 0; c < nchunk; c++) {
        if (c + 3 < nchunk) issue_chunk(c + 3, (c + 3) & 3);
        CP_COMMIT();
        asm volatile("cp.async.wait_group 3;");
        __syncthreads();

        const uint32_t sA = sbase + (uint32_t)(c & 3) * G2_STAGE;
        const uint32_t sB = sA + G2_ABYTES;

        #pragma unroll
        for (int ks = 0; ks < 2; ks++) {
            uint32_t a[4][4];
            #pragma unroll
            for (int mi = 0; mi < 4; mi++)
                LDSM4(a[mi], sA + (uint32_t)((wm * 64 + mi * 16 + l15) * HROW_B + ks * 32 + koff));
            uint32_t bf[4][4];
            #pragma unroll
            for (int g = 0; g < 4; g++)
                LDSM4(bf[g], sB + (uint32_t)((wn * 64 + g * 16 + l15) * HROW_B + ks * 32 + koff));
            #pragma unroll
            for (int mi = 0; mi < 4; mi++)
                #pragma unroll
                for (int g = 0; g < 4; g++)
                    #pragma unroll
                    for (int h = 0; h < 2; h++)
                        mma_f16(acc[mi][g * 2 + h], a[mi], bf[g][h], bf[g][h + 2]);
        }
        __syncthreads();
    }

    // Epilogue
    #pragma unroll
    for (int mi = 0; mi < 4; mi++) {
        const int row = m0 + wm * 64 + mi * 16 + gid;
        #pragma unroll
        for (int ni = 0; ni < 8; ni++) {
            const int col = n0 + wn * 64 + ni * 8 + tig * 2;
            const float b0v = bias[col], b1v = bias[col + 1];
            float v0 = acc[mi][ni][0] + b0v;
            float v1 = acc[mi][ni][1] + b1v;
            float v2 = acc[mi][ni][2] + b0v;
            float v3 = acc[mi][ni][3] + b1v;
            if (relu) {
                v0 = fmaxf(v0, 0.f); v1 = fmaxf(v1, 0.f);
                v2 = fmaxf(v2, 0.f); v3 = fmaxf(v3, 0.f);
            }
            if (qkv_split) {
                const int buf = col >> 11, colr = col & (HS_ - 1);
                __half* Ch = (__half*)Cout + (size_t)buf * NROWS * HS_;
                *(__half2*)(Ch + (size_t)row * HS_ + colr) = __floats2half2_rn(v0, v1);
                *(__half2*)(Ch + (size_t)(row + 8) * HS_ + colr) = __floats2half2_rn(v2, v3);
            } else if (out_half) {
                __half* Ch = (__half*)Cout;
                *(__half2*)(Ch + (size_t)row * N + col) = __floats2half2_rn(v0, v1);
                *(__half2*)(Ch + (size_t)(row + 8) * N + col) = __floats2half2_rn(v2, v3);
            } else {
                float* Cf = (float*)Cout;
                float2 o01; o01.x = v0; o01.y = v1;
                float2 o23; o23.x = v2; o23.y = v3;
                *(float2*)(Cf + (size_t)row * N + col) = o01;
                *(float2*)(Cf + (size_t)(row + 8) * N + col) = o23;
            }
        }
    }
}

// ---------------------------------------------------------------------------
// Wf2 GEMM + fused LayerNorm + mask + head-major half out.
// CTA 128 (rows) x 256 (FD). use_mask: 0 none, 1 always, 2 auto (rows>=NTOK=k).
// out: qfh base; k rows go to +NTOK*FD halves.
// ---------------------------------------------------------------------------
#define LNA_BYTES (128 * HROW_B)
#define LNB_BYTES (256 * HROW_B)
#define LN_STAGE  (LNA_BYTES + LNB_BYTES)
#define LN_SMEM   (2 * LN_STAGE)

__global__ __launch_bounds__(256, 1) void gemm_ln_kernel(
    const __half* __restrict__ A, const __half* __restrict__ BT,
    const float* __restrict__ bias, const float* __restrict__ gamma,
    const float* __restrict__ beta, const float* __restrict__ mask,
    __half* __restrict__ out, int use_mask)
{
    extern __shared__ char smraw[];
    const uint32_t sbase = smem_u32(smraw);
    float* smf = (float*)smraw;
    const int tid = threadIdx.x;
    const int wid = tid >> 5, lane = tid & 31;
    const int wm = wid & 1, wn = wid >> 1;
    const int gid = lane >> 2, tig = lane & 3;
    const int m0 = blockIdx.x * 128;
    const int K = FD_;

    float acc[4][8][4];
    #pragma unroll
    for (int mi = 0; mi < 4; mi++)
        #pragma unroll
        for (int ni = 0; ni < 8; ni++)
            #pragma unroll
            for (int j = 0; j < 4; j++) acc[mi][ni][j] = 0.f;

    auto issue_chunk = [&](int c, int slot) {
        const __half* Ag = A + (size_t)m0 * K + c * 32;
        const __half* Bg = BT + c * 32;
        const uint32_t sA = sbase + (uint32_t)slot * LN_STAGE;
        const uint32_t sB = sA + LNA_BYTES;
        #pragma unroll
        for (int r = 0; r < 2; r++) {
            const int idx = tid + 256 * r;
            const int row = idx >> 2, seg = idx & 3;
            CP_ASYNC16(sA + (uint32_t)(row * HROW_B + seg * 16),
                       Ag + (size_t)row * K + seg * 8);
        }
        #pragma unroll
        for (int r = 0; r < 4; r++) {
            const int idx = tid + 256 * r;
            const int row = idx >> 2, seg = idx & 3;
            CP_ASYNC16(sB + (uint32_t)(row * HROW_B + seg * 16),
                       Bg + (size_t)row * K + seg * 8);
        }
    };

    issue_chunk(0, 0); CP_COMMIT();

    const int l15 = lane & 15;
    const int koff = (lane >> 4) * 16;
    const int nchunk = K >> 5;

    for (int c = 0; c < nchunk; c++) {
        if (c + 1 < nchunk) {
            issue_chunk(c + 1, (c + 1) & 1); CP_COMMIT();
            asm volatile("cp.async.wait_group 1;");
        } else {
            asm volatile("cp.async.wait_group 0;");
        }
        __syncthreads();

        const uint32_t sA = sbase + (uint32_t)(c & 1) * LN_STAGE;
        const uint32_t sB = sA + LNA_BYTES;

        #pragma unroll
        for (int ks = 0; ks < 2; ks++) {
            uint32_t a[4][4];
            #pragma unroll
            for (int mi = 0; mi < 4; mi++)
                LDSM4(a[mi], sA + (uint32_t)((wm * 64 + mi * 16 + l15) * HROW_B + ks * 32 + koff));
            uint32_t bf[4][4];
            #pragma unroll
            for (int g = 0; g < 4; g++)
                LDSM4(bf[g], sB + (uint32_t)((wn * 64 + g * 16 + l15) * HROW_B + ks * 32 + koff));
            #pragma unroll
            for (int mi = 0; mi < 4; mi++)
                #pragma unroll
                for (int g = 0; g < 4; g++)
                    #pragma unroll
                    for (int h = 0; h < 2; h++)
                        mma_f16(acc[mi][g * 2 + h], a[mi], bf[g][h], bf[g][h + 2]);
        }
        __syncthreads();
    }

    #pragma unroll
    for (int mi = 0; mi < 4; mi++)
        #pragma unroll
        for (int ni = 0; ni < 8; ni++) {
            const int col = wn * 64 + ni * 8 + tig * 2;
            acc[mi][ni][0] += bias[col];
            acc[mi][ni][1] += bias[col + 1];
            acc[mi][ni][2] += bias[col];
            acc[mi][ni][3] += bias[col + 1];
        }

    float rsum[4][2], rsq[4][2];
    #pragma unroll
    for (int mi = 0; mi < 4; mi++) {
        float slo = 0.f, qlo = 0.f, shi = 0.f, qhi = 0.f;
        #pragma unroll
        for (int ni = 0; ni < 8; ni++) {
            slo += acc[mi][ni][0] + acc[mi][ni][1];
            qlo += acc[mi][ni][0] * acc[mi][ni][0] + acc[mi][ni][1] * acc[mi][ni][1];
            shi += acc[mi][ni][2] + acc[mi][ni][3];
            qhi += acc[mi][ni][2] * acc[mi][ni][2] + acc[mi][ni][3] * acc[mi][ni][3];
        }
        #pragma unroll
        for (int o = 1; o <= 2; o <<= 1) {
            slo += __shfl_xor_sync(0xffffffffu, slo, o);
            qlo += __shfl_xor_sync(0xffffffffu, qlo, o);
            shi += __shfl_xor_sync(0xffffffffu, shi, o);
            qhi += __shfl_xor_sync(0xffffffffu, qhi, o);
        }
        rsum[mi][0] = slo; rsq[mi][0] = qlo;
        rsum[mi][1] = shi; rsq[mi][1] = qhi;
    }

    if (tig == 0) {
        #pragma unroll
        for (int mi = 0; mi < 4; mi++) {
            const int rlo = wm * 64 + mi * 16 + gid;
            smf[rlo * 4 + wn] = rsum[mi][0];
            smf[512 + rlo * 4 + wn] = rsq[mi][0];
            smf[(rlo + 8) * 4 + wn] = rsum[mi][1];
            smf[512 + (rlo + 8) * 4 + wn] = rsq[mi][1];
        }
    }
    __syncthreads();

    #pragma unroll
    for (int mi = 0; mi < 4; mi++) {
        #pragma unroll
        for (int lh = 0; lh < 2; lh++) {
            const int rr = wm * 64 + mi * 16 + gid + lh * 8;
            float ts = smf[rr * 4 + 0] + smf[rr * 4 + 1] + smf[rr * 4 + 2] + smf[rr * 4 + 3];
            float tq = smf[512 + rr * 4 + 0] + smf[512 + rr * 4 + 1] +
                       smf[512 + rr * 4 + 2] + smf[512 + rr * 4 + 3];
            const float mu = ts * (1.f / FD_);
            const float var = tq * (1.f / FD_) - mu * mu;
            const float rstd = rsqrtf(var + 1e-5f);

            int tok = m0 + rr;
            const int is_k = (use_mask == 2) ? (tok >= NTOK) : 0;
            if (is_k) tok -= NTOK;
            const int h = tok & 15;
            const int bl = tok >> 4;
            const int l = bl & (L_ - 1);
            const int b = bl >> 12;
            float mscale = 1.f;
            if (use_mask == 1 || (use_mask == 2 && is_k)) mscale = 1.f + mask[bl];
            __half* orow = out + (size_t)is_k * ((size_t)NTOK * FD_) +
                           ((size_t)((b * NH_ + h)) * L_ + l) * FD_;

            #pragma unroll
            for (int ni = 0; ni < 8; ni++) {
                const int col = wn * 64 + ni * 8 + tig * 2;
                const float g0 = gamma[col], g1 = gamma[col + 1];
                const float be0 = beta[col], be1 = beta[col + 1];
                float y0 = ((acc[mi][ni][lh * 2 + 0] - mu) * rstd * g0 + be0) * mscale;
                float y1 = ((acc[mi][ni][lh * 2 + 1] - mu) * rstd * g1 + be1) * mscale;
                *(__half2*)(orow + col) = __floats2half2_rn(y0, y1);
            }
        }
    }
}

// ---------------------------------------------------------------------------
// kv via tensor cores (trans-ldmatrix), 8-way L split, fp32 partials.
// ---------------------------------------------------------------------------
#define KV_KFROW 528
#define KV_VROW  272
#define KV_STAGE (32 * KV_KFROW + 32 * KV_VROW)
#define KV_SMEM  (2 * KV_STAGE)

__global__ __launch_bounds__(256, 1) void kv_tc_kernel(
    const __half* __restrict__ kf, const __half* __restrict__ vh,
    float* __restrict__ kvp)
{
    extern __shared__ char smraw[];
    const uint32_t sbase = smem_u32(smraw);
    const int tid = threadIdx.x;
    const int wid = tid >> 5, lane = tid & 31;
    const int wm = wid & 3, wn = wid >> 2;
    const int gid = lane >> 2, tig = lane & 3;
    const int bh = blockIdx.x, split = blockIdx.y;
    const int b = bh >> 4, h = bh & 15;
    const int k0 = split * 512;

    const __half* kfb = kf + (size_t)bh * L_ * FD_;

    float acc[4][8][4];
    #pragma unroll
    for (int mi = 0; mi < 4; mi++)
        #pragma unroll
        for (int ni = 0; ni < 8; ni++)
            #pragma unroll
            for (int j = 0; j < 4; j++) acc[mi][ni][j] = 0.f;

    auto issue_chunk = [&](int c, int slot) {
        const int l0 = k0 + c * 32;
        const uint32_t sKF = sbase + (uint32_t)slot * KV_STAGE;
        const uint32_t sV = sKF + 32 * KV_KFROW;
        #pragma unroll
        for (int r = 0; r < 4; r++) {
            const int idx = tid + 256 * r;
            const int row = idx >> 5, seg = idx & 31;
            CP_ASYNC16(sKF + (uint32_t)(row * KV_KFROW + seg * 16),
                       kfb + (size_t)(l0 + row) * FD_ + seg * 8);
        }
        #pragma unroll
        for (int r = 0; r < 2; r++) {
            const int idx = tid + 256 * r;
            const int row = idx >> 4, seg = idx & 15;
            CP_ASYNC16(sV + (uint32_t)(row * KV_VROW + seg * 16),
                       vh + ((size_t)(b * L_ + l0 + row)) * HS_ + h * HD_ + seg * 8);
        }
    };

    issue_chunk(0, 0); CP_COMMIT();

    const int quad = lane >> 3, qr = lane & 7;
    const int nchunk = 16;

    for (int c = 0; c < nchunk; c++) {
        if (c + 1 < nchunk) {
            issue_chunk(c + 1, (c + 1) & 1); CP_COMMIT();
            asm volatile("cp.async.wait_group 1;");
        } else {
            asm volatile("cp.async.wait_group 0;");
        }
        __syncthreads();

        const uint32_t sKF = sbase + (uint32_t)(c & 1) * KV_STAGE;
        const uint32_t sV = sKF + 32 * KV_KFROW;

        #pragma unroll
        for (int ks = 0; ks < 2; ks++) {
            const int lrow = ks * 16 + (quad >> 1) * 8 + qr;
            const int coff = (quad & 1) * 8;
            uint32_t a[4][4];
            #pragma unroll
            for (int mi = 0; mi < 4; mi++) {
                const int f0 = wm * 64 + mi * 16;
                LDSM4T(a[mi], sKF + (uint32_t)(lrow * KV_KFROW + (f0 + coff) * 2));
            }
            uint32_t bf[4][4];
            #pragma unroll
            for (int g = 0; g < 4; g++) {
                const int d0 = wn * 64 + g * 16;
                LDSM4T(bf[g], sV + (uint32_t)(lrow * KV_VROW + (d0 + coff) * 2));
            }
            #pragma unroll
            for (int mi = 0; mi < 4; mi++)
                #pragma unroll
                for (int g = 0; g < 4; g++)
                    #pragma unroll
                    for (int hh = 0; hh < 2; hh++)
                        mma_f16(acc[mi][g * 2 + hh], a[mi], bf[g][hh], bf[g][hh + 2]);
        }
        __syncthreads();
    }

    float* outp = kvp + ((size_t)(split * BH_ + bh)) * HD_ * FD_;
    #pragma unroll
    for (int mi = 0; mi < 4; mi++) {
        const int m = wm * 64 + mi * 16 + gid;
        #pragma unroll
        for (int ni = 0; ni < 8; ni++) {
            const int n = wn * 64 + ni * 8 + tig * 2;
            outp[(size_t)n * FD_ + m]           = acc[mi][ni][0];
            outp[(size_t)(n + 1) * FD_ + m]     = acc[mi][ni][1];
            outp[(size_t)n * FD_ + m + 8]       = acc[mi][ni][2];
            outp[(size_t)(n + 1) * FD_ + m + 8] = acc[mi][ni][3];
        }
    }
}

__global__ __launch_bounds__(256) void kv_reduce_kernel(
    const float* __restrict__ kvp, __half* __restrict__ kvT)
{
    const int i = blockIdx.x * 256 + threadIdx.x;
    const size_t stride = (size_t)BH_ * HD_ * FD_;
    float4 s = *(const float4*)(kvp + (size_t)i * 4);
    #pragma unroll
    for (int p = 1; p < 8; p++) {
        float4 t = *(const float4*)(kvp + p * stride + (size_t)i * 4);
        s.x += t.x; s.y += t.y; s.z += t.z; s.w += t.w;
    }
    __half2 h0 = __floats2half2_rn(s.x, s.y);
    __half2 h1 = __floats2half2_rn(s.z, s.w);
    uint2 o;
    o.x = *(uint32_t*)&h0; o.y = *(uint32_t*)&h1;
    *(uint2*)(kvT + (size_t)i * 4) = o;
}

// ---------------------------------------------------------------------------
// ksum + denom
// ---------------------------------------------------------------------------
__global__ void zero_ksum_kernel(float* __restrict__ ks)
{
    ks[blockIdx.x * FD_ + threadIdx.x] = 0.f;
}

__global__ __launch_bounds__(256) void ksum_h_kernel(
    const __half* __restrict__ kf, float* __restrict__ ks)
{
    const int bh = blockIdx.x, chunk = blockIdx.y;
    const int f = threadIdx.x;
    const __half* base = kf + (size_t)bh * L_ * FD_ + (size_t)chunk * 512 * FD_ + f;
    float acc = 0.f;
    for (int l = 0; l < 512; ++l)
        acc += __half2float(base[(size_t)l * FD_]);
    atomicAdd(&ks[bh * FD_ + f], acc);
}

__global__ __launch_bounds__(256) void denom_kernel(
    const __half* __restrict__ qf, const float* __restrict__ ks,
    float* __restrict__ den)
{
    const int wid = threadIdx.x >> 5, lane = threadIdx.x & 31;
    const int r = blockIdx.x * 8 + wid;
    const int bh = r >> 12;
    const uint4 p = *(const uint4*)(qf + (size_t)r * FD_ + lane * 8);
    const float* kp = ks + bh * FD_ + lane * 8;
    const __half2* h = (const __half2*)&p;
    float acc = 0.f;
    #pragma unroll
    for (int j = 0; j < 4; j++) {
        float2 f2 = __half22float2(h[j]);
        acc += f2.x * kp[j * 2] + f2.y * kp[j * 2 + 1];
    }
    #pragma unroll
    for (int o = 16; o; o >>= 1) acc += __shfl_down_sync(0xffffffffu, acc, o);
    if (lane == 0) den[r] = acc;
}

// ---------------------------------------------------------------------------
// attn via tensor cores (128x128, K=256) with fused denominator
// ---------------------------------------------------------------------------
#define A_BYTES  (128 * HROW_B)
#define STAGE_BYTES (2 * A_BYTES)
#define GEMM_SMEM (3 * STAGE_BYTES)

__global__ __launch_bounds__(256, 2) void attn_tc_kernel(
    const __half* __restrict__ qf, const __half* __restrict__ kvT,
    const float* __restrict__ den, __half* __restrict__ out)
{
    extern __shared__ char smraw[];
    const uint32_t sbase = smem_u32(smraw);
    const int tid = threadIdx.x;
    const int wid = tid >> 5, lane = tid & 31;
    const int wm = wid & 3, wn = wid >> 2;
    const int gid = lane >> 2, tig = lane & 3;
    const int bh = blockIdx.x, l0 = blockIdx.y * 128;
    const int b = bh >> 4, h = bh & 15;
    const int K = FD_;

    const __half* A = qf + (size_t)bh * L_ * FD_ + (size_t)l0 * FD_;
    const __half* BT = kvT + (size_t)bh * HD_ * FD_;

    float acc[2][8][4];
    #pragma unroll
    for (int mi = 0; mi < 2; mi++)
        #pragma unroll
        for (int ni = 0; ni < 8; ni++)
            #pragma unroll
            for (int j = 0; j < 4; j++) acc[mi][ni][j] = 0.f;

    auto issue_chunk = [&](int c, int slot) {
        const uint32_t sA = sbase + (uint32_t)slot * STAGE_BYTES;
        const uint32_t sB = sA + A_BYTES;
        #pragma unroll
        for (int r = 0; r < 2; r++) {
            const int idx = tid + 256 * r;
            const int row = idx >> 2, seg = idx & 3;
            const uint32_t so = (uint32_t)(row * HROW_B + seg * 16);
            CP_ASYNC16(sA + so, A + (size_t)row * K + c * 32 + seg * 8);
            CP_ASYNC16(sB + so, BT + (size_t)row * K + c * 32 + seg * 8);
        }
    };

    issue_chunk(0, 0); CP_COMMIT();
    issue_chunk(1, 1); CP_COMMIT();

    const int l15 = lane & 15;
    const int koff = (lane >> 4) * 16;
    const int nchunk = K >> 5;

    int slot = 0;
    for (int c = 0; c < nchunk; c++) {
        if (c + 2 < nchunk) issue_chunk(c + 2, (c + 2) % 3);
        CP_COMMIT();
        asm volatile("cp.async.wait_group 2;");
        __syncthreads();

        const uint32_t sA = sbase + (uint32_t)slot * STAGE_BYTES;
        const uint32_t sB = sA + A_BYTES;

        #pragma unroll
        for (int ks = 0; ks < 2; ks++) {
            uint32_t a[2][4];
            #pragma unroll
            for (int mi = 0; mi < 2; mi++)
                LDSM4(a[mi], sA + (uint32_t)((wm * 32 + mi * 16 + l15) * HROW_B + ks * 32 + koff));
            uint32_t bf[4][4];
            #pragma unroll
            for (int g = 0; g < 4; g++)
                LDSM4(bf[g], sB + (uint32_t)((wn * 64 + g * 16 + l15) * HROW_B + ks * 32 + koff));
            #pragma unroll
            for (int g = 0; g < 4; g++)
                #pragma unroll
                for (int hh = 0; hh < 2; hh++) {
                    mma_f16(acc[0][g * 2 + hh], a[0], bf[g][hh], bf[g][hh + 2]);
                    mma_f16(acc[1][g * 2 + hh], a[1], bf[g][hh], bf[g][hh + 2]);
                }
        }
        __syncthreads();
        slot++; if (slot == 3) slot = 0;
    }

    #pragma unroll
    for (int mi = 0; mi < 2; mi++) {
        const int row = wm * 32 + mi * 16 + gid;
        const int llo = l0 + row, lhi = llo + 8;
        const float ilo = 1.f / (den[bh * L_ + llo] + 1e-8f);
        const float ihi = 1.f / (den[bh * L_ + lhi] + 1e-8f);
        __half* olo = out + ((size_t)(b * L_ + llo)) * HS_ + h * HD_;
        __half* ohi = out + ((size_t)(b * L_ + lhi)) * HS_ + h * HD_;
        #pragma unroll
        for (int ni = 0; ni < 8; ni++) {
            const int col = wn * 64 + ni * 8 + tig * 2;
            *(__half2*)(olo + col) = __floats2half2_rn(acc[mi][ni][0] * ilo,
                                                        acc[mi][ni][1] * ilo);
            *(__half2*)(ohi + col) = __floats2half2_rn(acc[mi][ni][2] * ihi,
                                                        acc[mi][ni][3] * ihi);
        }
    }
}

// ---------------------------------------------------------------------------
// Transpose to half + f2h
// ---------------------------------------------------------------------------
__global__ __launch_bounds__(256) void transpose_h_kernel(
    const float* __restrict__ src, __half* __restrict__ dst, int R, int C)
{
    __shared__ float t[32][33];
    const int bx = blockIdx.x * 32;
    const int by = blockIdx.y * 32;
    const int tx = threadIdx.x, ty = threadIdx.y;
    #pragma unroll
    for (int i = 0; i < 32; i += 8)
        t[ty + i][tx] = src[(size_t)(by + ty + i) * C + bx + tx];
    __syncthreads();
    #pragma unroll
    for (int i = 0; i < 32; i += 8)
        dst[(size_t)(bx + ty + i) * R + by + tx] = __float2half_rn(t[tx][ty + i]);
}

__global__ __launch_bounds__(256) void f2h_kernel(
    const float4* __restrict__ src, uint2* __restrict__ dst, int n4)
{
    const int i = blockIdx.x * 256 + threadIdx.x;
    if (i < n4) {
        float4 v = src[i];
        __half2 a = __floats2half2_rn(v.x, v.y);
        __half2 b = __floats2half2_rn(v.z, v.w);
        uint2 o;
        o.x = *(uint32_t*)&a;
        o.y = *(uint32_t*)&b;
        dst[i] = o;
    }
}

// ---------------------------------------------------------------------------
// Host launch
// ---------------------------------------------------------------------------
extern "C" void kernel_launch(void* const* d_in, const int* in_sizes, int n_in,
                              void* d_out, int out_size)
{
    (void)in_sizes; (void)n_in; (void)out_size;
    const float* X    = (const float*)d_in[0];
    const float* mask = (const float*)d_in[1];
    const float* Wq   = (const float*)d_in[2];
    const float* bq   = (const float*)d_in[3];
    const float* Wk   = (const float*)d_in[4];
    const float* bk   = (const float*)d_in[5];
    const float* Wv   = (const float*)d_in[6];
    const float* bv   = (const float*)d_in[7];
    const float* Wo   = (const float*)d_in[8];
    const float* bo   = (const float*)d_in[9];
    const float* Wf1  = (const float*)d_in[10];
    const float* bf1  = (const float*)d_in[11];
    const float* Wf2  = (const float*)d_in[12];
    const float* bf2  = (const float*)d_in[13];
    const float* ln_g = (const float*)d_in[14];
    const float* ln_b = (const float*)d_in[15];

    float* scratch = nullptr;
    cudaGetSymbolAddress((void**)&scratch, g_scratch);
    __half* Xh     = (__half*)(scratch + OFF_XH);
    __half* qkvh   = (__half*)(scratch + OFF_QKV);       // q | k | v
    __half* qh     = qkvh;
    __half* vh     = (__half*)(scratch + OFF_QKV + 16777216);
    __half* tmph   = (__half*)(scratch + OFF_TMPH);
    __half* qfh    = (__half*)(scratch + OFF_QFH);
    __half* kfh    = (__half*)(scratch + OFF_KFH);
    float*  kvp    = scratch + OFF_KVP;
    __half* kvT    = (__half*)(scratch + OFF_KVT);
    float*  ksbuf  = scratch + OFF_KSUM;
    float*  den    = scratch + OFF_DEN;
    __half* attnh  = (__half*)(scratch + OFF_ATTNH);
    __half* WqkvT  = (__half*)(scratch + OFF_WQKVT);
    __half* WoT    = (__half*)(scratch + OFF_WOT);
    __half* Wf1T   = (__half*)(scratch + OFF_WF1T);
    __half* Wf2T   = (__half*)(scratch + OFF_WF2T);
    float*  bqkv   = scratch + OFF_BQKV;

    static bool attr_set = false;
    if (!attr_set) {
        cudaFuncSetAttribute(gemm256_kernel,
                             cudaFuncAttributeMaxDynamicSharedMemorySize, G2_SMEM);
        cudaFuncSetAttribute(gemm_ln_kernel,
                             cudaFuncAttributeMaxDynamicSharedMemorySize, LN_SMEM);
        cudaFuncSetAttribute(kv_tc_kernel,
                             cudaFuncAttributeMaxDynamicSharedMemorySize, KV_SMEM);
        cudaFuncSetAttribute(attn_tc_kernel,
                             cudaFuncAttributeMaxDynamicSharedMemorySize, GEMM_SMEM);
        attr_set = true;
    }

    // Combined bias [bq|bk|bv]
    cudaMemcpyAsync(bqkv,            bq, HS_ * sizeof(float), cudaMemcpyDeviceToDevice);
    cudaMemcpyAsync(bqkv + HS_,      bk, HS_ * sizeof(float), cudaMemcpyDeviceToDevice);
    cudaMemcpyAsync(bqkv + 2 * HS_,  bv, HS_ * sizeof(float), cudaMemcpyDeviceToDevice);

    dim3 t8(32, 8);
    // Weight transposes into combined WqkvT [6144][2048] half
    transpose_h_kernel<<<dim3(HS_/32, HS_/32), t8>>>(Wq, WqkvT, HS_, HS_);
    transpose_h_kernel<<<dim3(HS_/32, HS_/32), t8>>>(Wk, WqkvT + (size_t)HS_*HS_, HS_, HS_);
    transpose_h_kernel<<<dim3(HS_/32, HS_/32), t8>>>(Wv, WqkvT + (size_t)2*HS_*HS_, HS_, HS_);
    transpose_h_kernel<<<dim3(HS_/32, HS_/32), t8>>>(Wo, WoT, HS_, HS_);
    transpose_h_kernel<<<dim3(FD_/32, HD_/32), t8>>>(Wf1, Wf1T, HD_, FD_);
    transpose_h_kernel<<<dim3(FD_/32, FD_/32), t8>>>(Wf2, Wf2T, FD_, FD_);

    f2h_kernel<<<(NROWS * HS_ / 4 + 255) / 256, 256>>>(
        (const float4*)X, (uint2*)Xh, NROWS * HS_ / 4);

    dim3 blk(256);

    // Fused QKV projection: [8192,2048] @ [6144,2048]^T -> q|k|v half buffers
    gemm256_kernel<<<dim3(3 * HS_ / 128, NROWS / 256), blk, G2_SMEM>>>(
        Xh, WqkvT, bqkv, qkvh, NROWS, 3 * HS_, HS_, 0, 1, 1);

    // Fused feature gemm1 for q&k: M = 2*NTOK (q rows then k rows)
    gemm256_kernel<<<dim3(FD_ / 128, 2 * NTOK / 256), blk, G2_SMEM>>>(
        qh, Wf1T, bf1, tmph, 2 * NTOK, FD_, HD_, 1, 1, 0);

    // Fused gemm2 + LN for q&k -> head-major qfh / kfh (auto mask)
    gemm_ln_kernel<<<2 * NTOK / 128, blk, LN_SMEM>>>(
        tmph, Wf2T, bf2, ln_g, ln_b, mask, qfh, 2);

    // k_sum
    zero_ksum_kernel<<<BH_, FD_>>>(ksbuf);
    ksum_h_kernel<<<dim3(BH_, 8), 256>>>(kfh, ksbuf);

    // kv (8-way L split) + reduce -> kvT half
    kv_tc_kernel<<<dim3(BH_, 8), blk, KV_SMEM>>>(kfh, vh, kvp);
    kv_reduce_kernel<<<1024, 256>>>(kvp, kvT);

    // denom
    denom_kernel<<<NTOK / 8, 256>>>(qfh, ksbuf, den);

    // attn -> tok-major half
    attn_tc_kernel<<<dim3(BH_, L_ / 128), blk, GEMM_SMEM>>>(qfh, kvT, den, attnh);

    // output projection (fp32 to d_out)
    gemm256_kernel<<<dim3(HS_ / 128, NROWS / 256), blk, G2_SMEM>>>(
        attnh, WoT, bo, (float*)d_out, NROWS, HS_, HS_, 0, 0, 0);
}

// round 13
// speedup vs baseline: 1.1416x; 1.1416x over previous
#include <cuda_runtime.h>
#include <cuda_fp16.h>
#include <cstdint>

// Problem constants
#define B_  2
#define L_  4096
#define HS_ 2048
#define NH_ 16
#define HD_ 128
#define FD_ 256
#define NROWS (B_*L_)            // 8192
#define NTOK  (B_*L_*NH_)        // 131072
#define BH_   (B_*NH_)           // 32

// Scratch layout (float units)
#define OFF_XH    ((size_t)0)                        // 8388608
#define OFF_QKV   ((size_t)8388608)                  // q|k|v each 8388608
#define OFF_TMPH  ((size_t)33554432)                 // 33554432 (262144x256 half)
#define OFF_QFH   ((size_t)67108864)                 // 16777216
#define OFF_KFH   ((size_t)83886080)                 // 16777216
#define OFF_KVP   ((size_t)100663296)                // 8388608
#define OFF_KVT   ((size_t)109051904)                // 524288
#define OFF_KSUM  ((size_t)109576192)                // 8192
#define OFF_DEN   ((size_t)109584384)                // 131072
#define OFF_ATTNH ((size_t)109715456)                // 8388608
#define OFF_WQKVT ((size_t)118104064)                // 6291456 (6144x2048 half)
#define OFF_WOT   ((size_t)124395520)                // 2097152
#define OFF_WF1T  ((size_t)126492672)                // 16384
#define OFF_WF2T  ((size_t)126509056)                // 32768
#define OFF_BQKV  ((size_t)126541824)                // 6144
#define SCRATCH_TOTAL ((size_t)126548992)

__device__ float g_scratch[SCRATCH_TOTAL];

// ---------------------------------------------------------------------------
// Helpers
// ---------------------------------------------------------------------------
__device__ __forceinline__ uint32_t smem_u32(const void* p) {
    uint32_t a;
    asm("{ .reg .u64 t; cvta.to.shared.u64 t, %1; cvt.u32.u64 %0, t; }"
        : "=r"(a) : "l"(p));
    return a;
}

#define CP_ASYNC16(saddr, gaddr) \
    asm volatile("cp.async.cg.shared.global [%0], [%1], 16;" \
                 :: "r"(saddr), "l"(gaddr))
#define CP_COMMIT() asm volatile("cp.async.commit_group;")

#define LDSM4(r, addr) \
    asm volatile("ldmatrix.sync.aligned.m8n8.x4.shared.b16 {%0,%1,%2,%3}, [%4];" \
                 : "=r"((r)[0]), "=r"((r)[1]), "=r"((r)[2]), "=r"((r)[3]) \
                 : "r"(addr))

#define LDSM4T(r, addr) \
    asm volatile("ldmatrix.sync.aligned.m8n8.x4.trans.shared.b16 {%0,%1,%2,%3}, [%4];" \
                 : "=r"((r)[0]), "=r"((r)[1]), "=r"((r)[2]), "=r"((r)[3]) \
                 : "r"(addr))

__device__ __forceinline__ void mma_f16(float* d, const uint32_t* a,
                                        uint32_t b0, uint32_t b1) {
    asm volatile(
        "mma.sync.aligned.m16n8k16.row.col.f32.f16.f16.f32 "
        "{%0,%1,%2,%3}, {%4,%5,%6,%7}, {%8,%9}, {%0,%1,%2,%3};"
        : "+f"(d[0]), "+f"(d[1]), "+f"(d[2]), "+f"(d[3])
        : "r"(a[0]), "r"(a[1]), "r"(a[2]), "r"(a[3]), "r"(b0), "r"(b1));
}

#define HROW_B   80

// ---------------------------------------------------------------------------
// fp16 tensor GEMM (R9-proven shape): C = A[M,K]@BT[N,K]^T + bias.
// CTA 128x128, BK=32, 8 warps (32x64), 3-stage cp.async, 2 CTAs/SM.
// qkv_split: route output columns (N=6144) into 3 [NROWS,HS] half buffers.
// ---------------------------------------------------------------------------
#define A_BYTES  (128 * HROW_B)
#define STAGE_BYTES (2 * A_BYTES)
#define GEMM_SMEM (3 * STAGE_BYTES)

__global__ __launch_bounds__(256, 2) void gemm_h_kernel(
    const __half* __restrict__ A, const __half* __restrict__ BT,
    const float* __restrict__ bias, void* __restrict__ Cout,
    int M, int N, int K, int relu, int out_half, int qkv_split)
{
    extern __shared__ char smraw[];
    const uint32_t sbase = smem_u32(smraw);
    const int tid = threadIdx.x;
    const int wid = tid >> 5, lane = tid & 31;
    const int wm = wid & 3, wn = wid >> 2;
    const int gid = lane >> 2, tig = lane & 3;
    const int n0 = blockIdx.x * 128, m0 = blockIdx.y * 128;

    float acc[2][8][4];
    #pragma unroll
    for (int mi = 0; mi < 2; mi++)
        #pragma unroll
        for (int ni = 0; ni < 8; ni++)
            #pragma unroll
            for (int j = 0; j < 4; j++) acc[mi][ni][j] = 0.f;

    const int nchunk = K >> 5;

    auto issue_chunk = [&](int c, int slot) {
        const __half* Ag = A + (size_t)m0 * K + c * 32;
        const __half* Bg = BT + (size_t)n0 * K + c * 32;
        const uint32_t sA = sbase + (uint32_t)slot * STAGE_BYTES;
        const uint32_t sB = sA + A_BYTES;
        #pragma unroll
        for (int r = 0; r < 2; r++) {
            const int idx = tid + 256 * r;
            const int row = idx >> 2, seg = idx & 3;
            const uint32_t so = (uint32_t)(row * HROW_B + seg * 16);
            CP_ASYNC16(sA + so, Ag + (size_t)row * K + seg * 8);
            CP_ASYNC16(sB + so, Bg + (size_t)row * K + seg * 8);
        }
    };

    issue_chunk(0, 0); CP_COMMIT();
    issue_chunk(1, 1); CP_COMMIT();

    const int l15 = lane & 15;
    const int koff = (lane >> 4) * 16;

    int slot = 0;
    for (int c = 0; c < nchunk; c++) {
        if (c + 2 < nchunk) issue_chunk(c + 2, (c + 2) % 3);
        CP_COMMIT();
        asm volatile("cp.async.wait_group 2;");
        __syncthreads();

        const uint32_t sA = sbase + (uint32_t)slot * STAGE_BYTES;
        const uint32_t sB = sA + A_BYTES;

        #pragma unroll
        for (int ks = 0; ks < 2; ks++) {
            uint32_t a[2][4];
            #pragma unroll
            for (int mi = 0; mi < 2; mi++)
                LDSM4(a[mi], sA + (uint32_t)((wm * 32 + mi * 16 + l15) * HROW_B + ks * 32 + koff));
            uint32_t bf[4][4];
            #pragma unroll
            for (int g = 0; g < 4; g++)
                LDSM4(bf[g], sB + (uint32_t)((wn * 64 + g * 16 + l15) * HROW_B + ks * 32 + koff));
            #pragma unroll
            for (int g = 0; g < 4; g++)
                #pragma unroll
                for (int h = 0; h < 2; h++) {
                    mma_f16(acc[0][g * 2 + h], a[0], bf[g][h], bf[g][h + 2]);
                    mma_f16(acc[1][g * 2 + h], a[1], bf[g][h], bf[g][h + 2]);
                }
        }
        __syncthreads();
        slot++; if (slot == 3) slot = 0;
    }

    #pragma unroll
    for (int mi = 0; mi < 2; mi++) {
        const int row = m0 + wm * 32 + mi * 16 + gid;
        #pragma unroll
        for (int ni = 0; ni < 8; ni++) {
            const int col = n0 + wn * 64 + ni * 8 + tig * 2;
            const float b0v = bias[col], b1v = bias[col + 1];
            float v0 = acc[mi][ni][0] + b0v;
            float v1 = acc[mi][ni][1] + b1v;
            float v2 = acc[mi][ni][2] + b0v;
            float v3 = acc[mi][ni][3] + b1v;
            if (relu) {
                v0 = fmaxf(v0, 0.f); v1 = fmaxf(v1, 0.f);
                v2 = fmaxf(v2, 0.f); v3 = fmaxf(v3, 0.f);
            }
            if (qkv_split) {
                const int buf = col >> 11, colr = col & (HS_ - 1);
                __half* Ch = (__half*)Cout + (size_t)buf * NROWS * HS_;
                *(__half2*)(Ch + (size_t)row * HS_ + colr) = __floats2half2_rn(v0, v1);
                *(__half2*)(Ch + (size_t)(row + 8) * HS_ + colr) = __floats2half2_rn(v2, v3);
            } else if (out_half) {
                __half* Ch = (__half*)Cout;
                *(__half2*)(Ch + (size_t)row * N + col) = __floats2half2_rn(v0, v1);
                *(__half2*)(Ch + (size_t)(row + 8) * N + col) = __floats2half2_rn(v2, v3);
            } else {
                float* Cf = (float*)Cout;
                float2 o01; o01.x = v0; o01.y = v1;
                float2 o23; o23.x = v2; o23.y = v3;
                *(float2*)(Cf + (size_t)row * N + col) = o01;
                *(float2*)(Cf + (size_t)(row + 8) * N + col) = o23;
            }
        }
    }
}

// ---------------------------------------------------------------------------
// Wf2 GEMM + fused LayerNorm + mask + head-major half out.
// CTA 128 (rows) x 256 (FD). use_mask: 2 = auto (rows >= NTOK are k; masked).
// ---------------------------------------------------------------------------
#define LNA_BYTES (128 * HROW_B)
#define LNB_BYTES (256 * HROW_B)
#define LN_STAGE  (LNA_BYTES + LNB_BYTES)
#define LN_SMEM   (2 * LN_STAGE)

__global__ __launch_bounds__(256, 1) void gemm_ln_kernel(
    const __half* __restrict__ A, const __half* __restrict__ BT,
    const float* __restrict__ bias, const float* __restrict__ gamma,
    const float* __restrict__ beta, const float* __restrict__ mask,
    __half* __restrict__ out, int use_mask)
{
    extern __shared__ char smraw[];
    const uint32_t sbase = smem_u32(smraw);
    float* smf = (float*)smraw;
    const int tid = threadIdx.x;
    const int wid = tid >> 5, lane = tid & 31;
    const int wm = wid & 1, wn = wid >> 1;
    const int gid = lane >> 2, tig = lane & 3;
    const int m0 = blockIdx.x * 128;
    const int K = FD_;

    float acc[4][8][4];
    #pragma unroll
    for (int mi = 0; mi < 4; mi++)
        #pragma unroll
        for (int ni = 0; ni < 8; ni++)
            #pragma unroll
            for (int j = 0; j < 4; j++) acc[mi][ni][j] = 0.f;

    auto issue_chunk = [&](int c, int slot) {
        const __half* Ag = A + (size_t)m0 * K + c * 32;
        const __half* Bg = BT + c * 32;
        const uint32_t sA = sbase + (uint32_t)slot * LN_STAGE;
        const uint32_t sB = sA + LNA_BYTES;
        #pragma unroll
        for (int r = 0; r < 2; r++) {
            const int idx = tid + 256 * r;
            const int row = idx >> 2, seg = idx & 3;
            CP_ASYNC16(sA + (uint32_t)(row * HROW_B + seg * 16),
                       Ag + (size_t)row * K + seg * 8);
        }
        #pragma unroll
        for (int r = 0; r < 4; r++) {
            const int idx = tid + 256 * r;
            const int row = idx >> 2, seg = idx & 3;
            CP_ASYNC16(sB + (uint32_t)(row * HROW_B + seg * 16),
                       Bg + (size_t)row * K + seg * 8);
        }
    };

    issue_chunk(0, 0); CP_COMMIT();

    const int l15 = lane & 15;
    const int koff = (lane >> 4) * 16;
    const int nchunk = K >> 5;

    for (int c = 0; c < nchunk; c++) {
        if (c + 1 < nchunk) {
            issue_chunk(c + 1, (c + 1) & 1); CP_COMMIT();
            asm volatile("cp.async.wait_group 1;");
        } else {
            asm volatile("cp.async.wait_group 0;");
        }
        __syncthreads();

        const uint32_t sA = sbase + (uint32_t)(c & 1) * LN_STAGE;
        const uint32_t sB = sA + LNA_BYTES;

        #pragma unroll
        for (int ks = 0; ks < 2; ks++) {
            uint32_t a[4][4];
            #pragma unroll
            for (int mi = 0; mi < 4; mi++)
                LDSM4(a[mi], sA + (uint32_t)((wm * 64 + mi * 16 + l15) * HROW_B + ks * 32 + koff));
            uint32_t bf[4][4];
            #pragma unroll
            for (int g = 0; g < 4; g++)
                LDSM4(bf[g], sB + (uint32_t)((wn * 64 + g * 16 + l15) * HROW_B + ks * 32 + koff));
            #pragma unroll
            for (int mi = 0; mi < 4; mi++)
                #pragma unroll
                for (int g = 0; g < 4; g++)
                    #pragma unroll
                    for (int h = 0; h < 2; h++)
                        mma_f16(acc[mi][g * 2 + h], a[mi], bf[g][h], bf[g][h + 2]);
        }
        __syncthreads();
    }

    #pragma unroll
    for (int mi = 0; mi < 4; mi++)
        #pragma unroll
        for (int ni = 0; ni < 8; ni++) {
            const int col = wn * 64 + ni * 8 + tig * 2;
            acc[mi][ni][0] += bias[col];
            acc[mi][ni][1] += bias[col + 1];
            acc[mi][ni][2] += bias[col];
            acc[mi][ni][3] += bias[col + 1];
        }

    float rsum[4][2], rsq[4][2];
    #pragma unroll
    for (int mi = 0; mi < 4; mi++) {
        float slo = 0.f, qlo = 0.f, shi = 0.f, qhi = 0.f;
        #pragma unroll
        for (int ni = 0; ni < 8; ni++) {
            slo += acc[mi][ni][0] + acc[mi][ni][1];
            qlo += acc[mi][ni][0] * acc[mi][ni][0] + acc[mi][ni][1] * acc[mi][ni][1];
            shi += acc[mi][ni][2] + acc[mi][ni][3];
            qhi += acc[mi][ni][2] * acc[mi][ni][2] + acc[mi][ni][3] * acc[mi][ni][3];
        }
        #pragma unroll
        for (int o = 1; o <= 2; o <<= 1) {
            slo += __shfl_xor_sync(0xffffffffu, slo, o);
            qlo += __shfl_xor_sync(0xffffffffu, qlo, o);
            shi += __shfl_xor_sync(0xffffffffu, shi, o);
            qhi += __shfl_xor_sync(0xffffffffu, qhi, o);
        }
        rsum[mi][0] = slo; rsq[mi][0] = qlo;
        rsum[mi][1] = shi; rsq[mi][1] = qhi;
    }

    if (tig == 0) {
        #pragma unroll
        for (int mi = 0; mi < 4; mi++) {
            const int rlo = wm * 64 + mi * 16 + gid;
            smf[rlo * 4 + wn] = rsum[mi][0];
            smf[512 + rlo * 4 + wn] = rsq[mi][0];
            smf[(rlo + 8) * 4 + wn] = rsum[mi][1];
            smf[512 + (rlo + 8) * 4 + wn] = rsq[mi][1];
        }
    }
    __syncthreads();

    #pragma unroll
    for (int mi = 0; mi < 4; mi++) {
        #pragma unroll
        for (int lh = 0; lh < 2; lh++) {
            const int rr = wm * 64 + mi * 16 + gid + lh * 8;
            float ts = smf[rr * 4 + 0] + smf[rr * 4 + 1] + smf[rr * 4 + 2] + smf[rr * 4 + 3];
            float tq = smf[512 + rr * 4 + 0] + smf[512 + rr * 4 + 1] +
                       smf[512 + rr * 4 + 2] + smf[512 + rr * 4 + 3];
            const float mu = ts * (1.f / FD_);
            const float var = tq * (1.f / FD_) - mu * mu;
            const float rstd = rsqrtf(var + 1e-5f);

            int tok = m0 + rr;
            const int is_k = (use_mask == 2) ? (tok >= NTOK) : 0;
            if (is_k) tok -= NTOK;
            const int h = tok & 15;
            const int bl = tok >> 4;
            const int l = bl & (L_ - 1);
            const int b = bl >> 12;
            float mscale = 1.f;
            if (use_mask == 1 || (use_mask == 2 && is_k)) mscale = 1.f + mask[bl];
            __half* orow = out + (size_t)is_k * ((size_t)NTOK * FD_) +
                           ((size_t)((b * NH_ + h)) * L_ + l) * FD_;

            #pragma unroll
            for (int ni = 0; ni < 8; ni++) {
                const int col = wn * 64 + ni * 8 + tig * 2;
                const float g0 = gamma[col], g1 = gamma[col + 1];
                const float be0 = beta[col], be1 = beta[col + 1];
                float y0 = ((acc[mi][ni][lh * 2 + 0] - mu) * rstd * g0 + be0) * mscale;
                float y1 = ((acc[mi][ni][lh * 2 + 1] - mu) * rstd * g1 + be1) * mscale;
                *(__half2*)(orow + col) = __floats2half2_rn(y0, y1);
            }
        }
    }
}

// ---------------------------------------------------------------------------
// kv via tensor cores (trans-ldmatrix), 8-way L split, fp32 partials.
// ---------------------------------------------------------------------------
#define KV_KFROW 528
#define KV_VROW  272
#define KV_STAGE (32 * KV_KFROW + 32 * KV_VROW)
#define KV_SMEM  (2 * KV_STAGE)

__global__ __launch_bounds__(256, 1) void kv_tc_kernel(
    const __half* __restrict__ kf, const __half* __restrict__ vh,
    float* __restrict__ kvp)
{
    extern __shared__ char smraw[];
    const uint32_t sbase = smem_u32(smraw);
    const int tid = threadIdx.x;
    const int wid = tid >> 5, lane = tid & 31;
    const int wm = wid & 3, wn = wid >> 2;
    const int gid = lane >> 2, tig = lane & 3;
    const int bh = blockIdx.x, split = blockIdx.y;
    const int b = bh >> 4, h = bh & 15;
    const int k0 = split * 512;

    const __half* kfb = kf + (size_t)bh * L_ * FD_;

    float acc[4][8][4];
    #pragma unroll
    for (int mi = 0; mi < 4; mi++)
        #pragma unroll
        for (int ni = 0; ni < 8; ni++)
            #pragma unroll
            for (int j = 0; j < 4; j++) acc[mi][ni][j] = 0.f;

    auto issue_chunk = [&](int c, int slot) {
        const int l0 = k0 + c * 32;
        const uint32_t sKF = sbase + (uint32_t)slot * KV_STAGE;
        const uint32_t sV = sKF + 32 * KV_KFROW;
        #pragma unroll
        for (int r = 0; r < 4; r++) {
            const int idx = tid + 256 * r;
            const int row = idx >> 5, seg = idx & 31;
            CP_ASYNC16(sKF + (uint32_t)(row * KV_KFROW + seg * 16),
                       kfb + (size_t)(l0 + row) * FD_ + seg * 8);
        }
        #pragma unroll
        for (int r = 0; r < 2; r++) {
            const int idx = tid + 256 * r;
            const int row = idx >> 4, seg = idx & 15;
            CP_ASYNC16(sV + (uint32_t)(row * KV_VROW + seg * 16),
                       vh + ((size_t)(b * L_ + l0 + row)) * HS_ + h * HD_ + seg * 8);
        }
    };

    issue_chunk(0, 0); CP_COMMIT();

    const int quad = lane >> 3, qr = lane & 7;
    const int nchunk = 16;

    for (int c = 0; c < nchunk; c++) {
        if (c + 1 < nchunk) {
            issue_chunk(c + 1, (c + 1) & 1); CP_COMMIT();
            asm volatile("cp.async.wait_group 1;");
        } else {
            asm volatile("cp.async.wait_group 0;");
        }
        __syncthreads();

        const uint32_t sKF = sbase + (uint32_t)(c & 1) * KV_STAGE;
        const uint32_t sV = sKF + 32 * KV_KFROW;

        #pragma unroll
        for (int ks = 0; ks < 2; ks++) {
            const int lrow = ks * 16 + (quad >> 1) * 8 + qr;
            const int coff = (quad & 1) * 8;
            uint32_t a[4][4];
            #pragma unroll
            for (int mi = 0; mi < 4; mi++) {
                const int f0 = wm * 64 + mi * 16;
                LDSM4T(a[mi], sKF + (uint32_t)(lrow * KV_KFROW + (f0 + coff) * 2));
            }
            uint32_t bf[4][4];
            #pragma unroll
            for (int g = 0; g < 4; g++) {
                const int d0 = wn * 64 + g * 16;
                LDSM4T(bf[g], sV + (uint32_t)(lrow * KV_VROW + (d0 + coff) * 2));
            }
            #pragma unroll
            for (int mi = 0; mi < 4; mi++)
                #pragma unroll
                for (int g = 0; g < 4; g++)
                    #pragma unroll
                    for (int hh = 0; hh < 2; hh++)
                        mma_f16(acc[mi][g * 2 + hh], a[mi], bf[g][hh], bf[g][hh + 2]);
        }
        __syncthreads();
    }

    float* outp = kvp + ((size_t)(split * BH_ + bh)) * HD_ * FD_;
    #pragma unroll
    for (int mi = 0; mi < 4; mi++) {
        const int m = wm * 64 + mi * 16 + gid;
        #pragma unroll
        for (int ni = 0; ni < 8; ni++) {
            const int n = wn * 64 + ni * 8 + tig * 2;
            outp[(size_t)n * FD_ + m]           = acc[mi][ni][0];
            outp[(size_t)(n + 1) * FD_ + m]     = acc[mi][ni][1];
            outp[(size_t)n * FD_ + m + 8]       = acc[mi][ni][2];
            outp[(size_t)(n + 1) * FD_ + m + 8] = acc[mi][ni][3];
        }
    }
}

__global__ __launch_bounds__(256) void kv_reduce_kernel(
    const float* __restrict__ kvp, __half* __restrict__ kvT)
{
    const int i = blockIdx.x * 256 + threadIdx.x;
    const size_t stride = (size_t)BH_ * HD_ * FD_;
    float4 s = *(const float4*)(kvp + (size_t)i * 4);
    #pragma unroll
    for (int p = 1; p < 8; p++) {
        float4 t = *(const float4*)(kvp + p * stride + (size_t)i * 4);
        s.x += t.x; s.y += t.y; s.z += t.z; s.w += t.w;
    }
    __half2 h0 = __floats2half2_rn(s.x, s.y);
    __half2 h1 = __floats2half2_rn(s.z, s.w);
    uint2 o;
    o.x = *(uint32_t*)&h0; o.y = *(uint32_t*)&h1;
    *(uint2*)(kvT + (size_t)i * 4) = o;
}

// ---------------------------------------------------------------------------
// ksum + denom
// ---------------------------------------------------------------------------
__global__ void zero_ksum_kernel(float* __restrict__ ks)
{
    ks[blockIdx.x * FD_ + threadIdx.x] = 0.f;
}

__global__ __launch_bounds__(256) void ksum_h_kernel(
    const __half* __restrict__ kf, float* __restrict__ ks)
{
    const int bh = blockIdx.x, chunk = blockIdx.y;
    const int f = threadIdx.x;
    const __half* base = kf + (size_t)bh * L_ * FD_ + (size_t)chunk * 512 * FD_ + f;
    float acc = 0.f;
    for (int l = 0; l < 512; ++l)
        acc += __half2float(base[(size_t)l * FD_]);
    atomicAdd(&ks[bh * FD_ + f], acc);
}

__global__ __launch_bounds__(256) void denom_kernel(
    const __half* __restrict__ qf, const float* __restrict__ ks,
    float* __restrict__ den)
{
    const int wid = threadIdx.x >> 5, lane = threadIdx.x & 31;
    const int r = blockIdx.x * 8 + wid;
    const int bh = r >> 12;
    const uint4 p = *(const uint4*)(qf + (size_t)r * FD_ + lane * 8);
    const float* kp = ks + bh * FD_ + lane * 8;
    const __half2* h = (const __half2*)&p;
    float acc = 0.f;
    #pragma unroll
    for (int j = 0; j < 4; j++) {
        float2 f2 = __half22float2(h[j]);
        acc += f2.x * kp[j * 2] + f2.y * kp[j * 2 + 1];
    }
    #pragma unroll
    for (int o = 16; o; o >>= 1) acc += __shfl_down_sync(0xffffffffu, acc, o);
    if (lane == 0) den[r] = acc;
}

// ---------------------------------------------------------------------------
// attn via tensor cores (128x128, K=256) with fused denominator
// ---------------------------------------------------------------------------
__global__ __launch_bounds__(256, 2) void attn_tc_kernel(
    const __half* __restrict__ qf, const __half* __restrict__ kvT,
    const float* __restrict__ den, __half* __restrict__ out)
{
    extern __shared__ char smraw[];
    const uint32_t sbase = smem_u32(smraw);
    const int tid = threadIdx.x;
    const int wid = tid >> 5, lane = tid & 31;
    const int wm = wid & 3, wn = wid >> 2;
    const int gid = lane >> 2, tig = lane & 3;
    const int bh = blockIdx.x, l0 = blockIdx.y * 128;
    const int b = bh >> 4, h = bh & 15;
    const int K = FD_;

    const __half* A = qf + (size_t)bh * L_ * FD_ + (size_t)l0 * FD_;
    const __half* BT = kvT + (size_t)bh * HD_ * FD_;

    float acc[2][8][4];
    #pragma unroll
    for (int mi = 0; mi < 2; mi++)
        #pragma unroll
        for (int ni = 0; ni < 8; ni++)
            #pragma unroll
            for (int j = 0; j < 4; j++) acc[mi][ni][j] = 0.f;

    auto issue_chunk = [&](int c, int slot) {
        const uint32_t sA = sbase + (uint32_t)slot * STAGE_BYTES;
        const uint32_t sB = sA + A_BYTES;
        #pragma unroll
        for (int r = 0; r < 2; r++) {
            const int idx = tid + 256 * r;
            const int row = idx >> 2, seg = idx & 3;
            const uint32_t so = (uint32_t)(row * HROW_B + seg * 16);
            CP_ASYNC16(sA + so, A + (size_t)row * K + c * 32 + seg * 8);
            CP_ASYNC16(sB + so, BT + (size_t)row * K + c * 32 + seg * 8);
        }
    };

    issue_chunk(0, 0); CP_COMMIT();
    issue_chunk(1, 1); CP_COMMIT();

    const int l15 = lane & 15;
    const int koff = (lane >> 4) * 16;
    const int nchunk = K >> 5;

    int slot = 0;
    for (int c = 0; c < nchunk; c++) {
        if (c + 2 < nchunk) issue_chunk(c + 2, (c + 2) % 3);
        CP_COMMIT();
        asm volatile("cp.async.wait_group 2;");
        __syncthreads();

        const uint32_t sA = sbase + (uint32_t)slot * STAGE_BYTES;
        const uint32_t sB = sA + A_BYTES;

        #pragma unroll
        for (int ks = 0; ks < 2; ks++) {
            uint32_t a[2][4];
            #pragma unroll
            for (int mi = 0; mi < 2; mi++)
                LDSM4(a[mi], sA + (uint32_t)((wm * 32 + mi * 16 + l15) * HROW_B + ks * 32 + koff));
            uint32_t bf[4][4];
            #pragma unroll
            for (int g = 0; g < 4; g++)
                LDSM4(bf[g], sB + (uint32_t)((wn * 64 + g * 16 + l15) * HROW_B + ks * 32 + koff));
            #pragma unroll
            for (int g = 0; g < 4; g++)
                #pragma unroll
                for (int hh = 0; hh < 2; hh++) {
                    mma_f16(acc[0][g * 2 + hh], a[0], bf[g][hh], bf[g][hh + 2]);
                    mma_f16(acc[1][g * 2 + hh], a[1], bf[g][hh], bf[g][hh + 2]);
                }
        }
        __syncthreads();
        slot++; if (slot == 3) slot = 0;
    }

    #pragma unroll
    for (int mi = 0; mi < 2; mi++) {
        const int row = wm * 32 + mi * 16 + gid;
        const int llo = l0 + row, lhi = llo + 8;
        const float ilo = 1.f / (den[bh * L_ + llo] + 1e-8f);
        const float ihi = 1.f / (den[bh * L_ + lhi] + 1e-8f);
        __half* olo = out + ((size_t)(b * L_ + llo)) * HS_ + h * HD_;
        __half* ohi = out + ((size_t)(b * L_ + lhi)) * HS_ + h * HD_;
        #pragma unroll
        for (int ni = 0; ni < 8; ni++) {
            const int col = wn * 64 + ni * 8 + tig * 2;
            *(__half2*)(olo + col) = __floats2half2_rn(acc[mi][ni][0] * ilo,
                                                        acc[mi][ni][1] * ilo);
            *(__half2*)(ohi + col) = __floats2half2_rn(acc[mi][ni][2] * ihi,
                                                        acc[mi][ni][3] * ihi);
        }
    }
}

// ---------------------------------------------------------------------------
// Transpose to half + f2h
// ---------------------------------------------------------------------------
__global__ __launch_bounds__(256) void transpose_h_kernel(
    const float* __restrict__ src, __half* __restrict__ dst, int R, int C)
{
    __shared__ float t[32][33];
    const int bx = blockIdx.x * 32;
    const int by = blockIdx.y * 32;
    const int tx = threadIdx.x, ty = threadIdx.y;
    #pragma unroll
    for (int i = 0; i < 32; i += 8)
        t[ty + i][tx] = src[(size_t)(by + ty + i) * C + bx + tx];
    __syncthreads();
    #pragma unroll
    for (int i = 0; i < 32; i += 8)
        dst[(size_t)(bx + ty + i) * R + by + tx] = __float2half_rn(t[tx][ty + i]);
}

__global__ __launch_bounds__(256) void f2h_kernel(
    const float4* __restrict__ src, uint2* __restrict__ dst, int n4)
{
    const int i = blockIdx.x * 256 + threadIdx.x;
    if (i < n4) {
        float4 v = src[i];
        __half2 a = __floats2half2_rn(v.x, v.y);
        __half2 b = __floats2half2_rn(v.z, v.w);
        uint2 o;
        o.x = *(uint32_t*)&a;
        o.y = *(uint32_t*)&b;
        dst[i] = o;
    }
}

// ---------------------------------------------------------------------------
// Host launch
// ---------------------------------------------------------------------------
extern "C" void kernel_launch(void* const* d_in, const int* in_sizes, int n_in,
                              void* d_out, int out_size)
{
    (void)in_sizes; (void)n_in; (void)out_size;
    const float* X    = (const float*)d_in[0];
    const float* mask = (const float*)d_in[1];
    const float* Wq   = (const float*)d_in[2];
    const float* bq   = (const float*)d_in[3];
    const float* Wk   = (const float*)d_in[4];
    const float* bk   = (const float*)d_in[5];
    const float* Wv   = (const float*)d_in[6];
    const float* bv   = (const float*)d_in[7];
    const float* Wo   = (const float*)d_in[8];
    const float* bo   = (const float*)d_in[9];
    const float* Wf1  = (const float*)d_in[10];
    const float* bf1  = (const float*)d_in[11];
    const float* Wf2  = (const float*)d_in[12];
    const float* bf2  = (const float*)d_in[13];
    const float* ln_g = (const float*)d_in[14];
    const float* ln_b = (const float*)d_in[15];

    float* scratch = nullptr;
    cudaGetSymbolAddress((void**)&scratch, g_scratch);
    __half* Xh     = (__half*)(scratch + OFF_XH);
    __half* qkvh   = (__half*)(scratch + OFF_QKV);       // q | k | v
    __half* qh     = qkvh;
    __half* vh     = (__half*)(scratch + OFF_QKV + 16777216);
    __half* tmph   = (__half*)(scratch + OFF_TMPH);
    __half* qfh    = (__half*)(scratch + OFF_QFH);
    __half* kfh    = (__half*)(scratch + OFF_KFH);
    float*  kvp    = scratch + OFF_KVP;
    __half* kvT    = (__half*)(scratch + OFF_KVT);
    float*  ksbuf  = scratch + OFF_KSUM;
    float*  den    = scratch + OFF_DEN;
    __half* attnh  = (__half*)(scratch + OFF_ATTNH);
    __half* WqkvT  = (__half*)(scratch + OFF_WQKVT);
    __half* WoT    = (__half*)(scratch + OFF_WOT);
    __half* Wf1T   = (__half*)(scratch + OFF_WF1T);
    __half* Wf2T   = (__half*)(scratch + OFF_WF2T);
    float*  bqkv   = scratch + OFF_BQKV;

    static bool attr_set = false;
    if (!attr_set) {
        cudaFuncSetAttribute(gemm_h_kernel,
                             cudaFuncAttributeMaxDynamicSharedMemorySize, GEMM_SMEM);
        cudaFuncSetAttribute(gemm_ln_kernel,
                             cudaFuncAttributeMaxDynamicSharedMemorySize, LN_SMEM);
        cudaFuncSetAttribute(kv_tc_kernel,
                             cudaFuncAttributeMaxDynamicSharedMemorySize, KV_SMEM);
        cudaFuncSetAttribute(attn_tc_kernel,
                             cudaFuncAttributeMaxDynamicSharedMemorySize, GEMM_SMEM);
        attr_set = true;
    }

    // Combined bias [bq|bk|bv]
    cudaMemcpyAsync(bqkv,            bq, HS_ * sizeof(float), cudaMemcpyDeviceToDevice);
    cudaMemcpyAsync(bqkv + HS_,      bk, HS_ * sizeof(float), cudaMemcpyDeviceToDevice);
    cudaMemcpyAsync(bqkv + 2 * HS_,  bv, HS_ * sizeof(float), cudaMemcpyDeviceToDevice);

    dim3 t8(32, 8);
    // Weight transposes into combined WqkvT [6144][2048] half
    transpose_h_kernel<<<dim3(HS_/32, HS_/32), t8>>>(Wq, WqkvT, HS_, HS_);
    transpose_h_kernel<<<dim3(HS_/32, HS_/32), t8>>>(Wk, WqkvT + (size_t)HS_*HS_, HS_, HS_);
    transpose_h_kernel<<<dim3(HS_/32, HS_/32), t8>>>(Wv, WqkvT + (size_t)2*HS_*HS_, HS_, HS_);
    transpose_h_kernel<<<dim3(HS_/32, HS_/32), t8>>>(Wo, WoT, HS_, HS_);
    transpose_h_kernel<<<dim3(FD_/32, HD_/32), t8>>>(Wf1, Wf1T, HD_, FD_);
    transpose_h_kernel<<<dim3(FD_/32, FD_/32), t8>>>(Wf2, Wf2T, FD_, FD_);

    f2h_kernel<<<(NROWS * HS_ / 4 + 255) / 256, 256>>>(
        (const float4*)X, (uint2*)Xh, NROWS * HS_ / 4);

    dim3 blk(256);

    // Fused QKV projection: [8192,2048] @ [6144,2048]^T -> q|k|v half buffers
    gemm_h_kernel<<<dim3(3 * HS_ / 128, NROWS / 128), blk, GEMM_SMEM>>>(
        Xh, WqkvT, bqkv, qkvh, NROWS, 3 * HS_, HS_, 0, 1, 1);

    // Fused feature gemm1 for q&k: M = 2*NTOK (q rows then k rows)
    gemm_h_kernel<<<dim3(FD_ / 128, 2 * NTOK / 128), blk, GEMM_SMEM>>>(
        qh, Wf1T, bf1, tmph, 2 * NTOK, FD_, HD_, 1, 1, 0);

    // Fused gemm2 + LN for q&k -> head-major qfh / kfh (auto mask)
    gemm_ln_kernel<<<2 * NTOK / 128, blk, LN_SMEM>>>(
        tmph, Wf2T, bf2, ln_g, ln_b, mask, qfh, 2);

    // k_sum
    zero_ksum_kernel<<<BH_, FD_>>>(ksbuf);
    ksum_h_kernel<<<dim3(BH_, 8), 256>>>(kfh, ksbuf);

    // kv (8-way L split) + reduce -> kvT half
    kv_tc_kernel<<<dim3(BH_, 8), blk, KV_SMEM>>>(kfh, vh, kvp);
    kv_reduce_kernel<<<1024, 256>>>(kvp, kvT);

    // denom
    denom_kernel<<<NTOK / 8, 256>>>(qfh, ksbuf, den);

    // attn -> tok-major half
    attn_tc_kernel<<<dim3(BH_, L_ / 128), blk, GEMM_SMEM>>>(qfh, kvT, den, attnh);

    // output projection (fp32 to d_out)
    gemm_h_kernel<<<dim3(HS_ / 128, NROWS / 128), blk, GEMM_SMEM>>>(
        attnh, WoT, bo, (float*)d_out, NROWS, HS_, HS_, 0, 0, 0);
}

// round 14
// speedup vs baseline: 1.1579x; 1.0143x over previous
#include <cuda_runtime.h>
#include <cuda_fp16.h>
#include <cstdint>

// Problem constants
#define B_  2
#define L_  4096
#define HS_ 2048
#define NH_ 16
#define HD_ 128
#define FD_ 256
#define NROWS (B_*L_)            // 8192
#define NTOK  (B_*L_*NH_)        // 131072
#define BH_   (B_*NH_)           // 32

// Scratch layout (float units)
#define OFF_XH    ((size_t)0)                        // 8388608
#define OFF_QKV   ((size_t)8388608)                  // q|k|v each 8388608
#define OFF_TMPH  ((size_t)33554432)                 // 33554432 (262144x256 half)
#define OFF_QFH   ((size_t)67108864)                 // 16777216
#define OFF_KFH   ((size_t)83886080)                 // 16777216
#define OFF_KVP   ((size_t)100663296)                // 8388608
#define OFF_KVT   ((size_t)109051904)                // 524288
#define OFF_KSUM  ((size_t)109576192)                // 8192
#define OFF_DEN   ((size_t)109584384)                // 131072
#define OFF_ATTNH ((size_t)109715456)                // 8388608
#define OFF_WQKVT ((size_t)118104064)                // 6291456 (6144x2048 half)
#define OFF_WOT   ((size_t)124395520)                // 2097152
#define OFF_WF1T  ((size_t)126492672)                // 16384
#define OFF_WF2T  ((size_t)126509056)                // 32768
#define OFF_BQKV  ((size_t)126541824)                // 6144
#define SCRATCH_TOTAL ((size_t)126548992)

__device__ float g_scratch[SCRATCH_TOTAL];

// ---------------------------------------------------------------------------
// Helpers
// ---------------------------------------------------------------------------
__device__ __forceinline__ uint32_t smem_u32(const void* p) {
    uint32_t a;
    asm("{ .reg .u64 t; cvta.to.shared.u64 t, %1; cvt.u32.u64 %0, t; }"
        : "=r"(a) : "l"(p));
    return a;
}

#define CP_ASYNC16(saddr, gaddr) \
    asm volatile("cp.async.cg.shared.global [%0], [%1], 16;" \
                 :: "r"(saddr), "l"(gaddr))
#define CP_COMMIT() asm volatile("cp.async.commit_group;")

#define LDSM4(r, addr) \
    asm volatile("ldmatrix.sync.aligned.m8n8.x4.shared.b16 {%0,%1,%2,%3}, [%4];" \
                 : "=r"((r)[0]), "=r"((r)[1]), "=r"((r)[2]), "=r"((r)[3]) \
                 : "r"(addr))

#define LDSM4T(r, addr) \
    asm volatile("ldmatrix.sync.aligned.m8n8.x4.trans.shared.b16 {%0,%1,%2,%3}, [%4];" \
                 : "=r"((r)[0]), "=r"((r)[1]), "=r"((r)[2]), "=r"((r)[3]) \
                 : "r"(addr))

__device__ __forceinline__ void mma_f16(float* d, const uint32_t* a,
                                        uint32_t b0, uint32_t b1) {
    asm volatile(
        "mma.sync.aligned.m16n8k16.row.col.f32.f16.f16.f32 "
        "{%0,%1,%2,%3}, {%4,%5,%6,%7}, {%8,%9}, {%0,%1,%2,%3};"
        : "+f"(d[0]), "+f"(d[1]), "+f"(d[2]), "+f"(d[3])
        : "r"(a[0]), "r"(a[1]), "r"(a[2]), "r"(a[3]), "r"(b0), "r"(b1));
}

#define HROW_B   80

// ---------------------------------------------------------------------------
// fp16 tensor GEMM (proven): C = A[M,K]@BT[N,K]^T + bias.
// CTA 128x128, BK=32, 8 warps (32x64), 3-stage cp.async, 2 CTAs/SM.
// qkv_split: route output columns (N=6144) into 3 [NROWS,HS] half buffers.
// ---------------------------------------------------------------------------
#define A_BYTES  (128 * HROW_B)
#define STAGE_BYTES (2 * A_BYTES)
#define GEMM_SMEM (3 * STAGE_BYTES)

__global__ __launch_bounds__(256, 2) void gemm_h_kernel(
    const __half* __restrict__ A, const __half* __restrict__ BT,
    const float* __restrict__ bias, void* __restrict__ Cout,
    int M, int N, int K, int relu, int out_half, int qkv_split)
{
    extern __shared__ char smraw[];
    const uint32_t sbase = smem_u32(smraw);
    const int tid = threadIdx.x;
    const int wid = tid >> 5, lane = tid & 31;
    const int wm = wid & 3, wn = wid >> 2;
    const int gid = lane >> 2, tig = lane & 3;
    const int n0 = blockIdx.x * 128, m0 = blockIdx.y * 128;

    float acc[2][8][4];
    #pragma unroll
    for (int mi = 0; mi < 2; mi++)
        #pragma unroll
        for (int ni = 0; ni < 8; ni++)
            #pragma unroll
            for (int j = 0; j < 4; j++) acc[mi][ni][j] = 0.f;

    const int nchunk = K >> 5;

    auto issue_chunk = [&](int c, int slot) {
        const __half* Ag = A + (size_t)m0 * K + c * 32;
        const __half* Bg = BT + (size_t)n0 * K + c * 32;
        const uint32_t sA = sbase + (uint32_t)slot * STAGE_BYTES;
        const uint32_t sB = sA + A_BYTES;
        #pragma unroll
        for (int r = 0; r < 2; r++) {
            const int idx = tid + 256 * r;
            const int row = idx >> 2, seg = idx & 3;
            const uint32_t so = (uint32_t)(row * HROW_B + seg * 16);
            CP_ASYNC16(sA + so, Ag + (size_t)row * K + seg * 8);
            CP_ASYNC16(sB + so, Bg + (size_t)row * K + seg * 8);
        }
    };

    issue_chunk(0, 0); CP_COMMIT();
    issue_chunk(1, 1); CP_COMMIT();

    const int l15 = lane & 15;
    const int koff = (lane >> 4) * 16;

    int slot = 0;
    for (int c = 0; c < nchunk; c++) {
        if (c + 2 < nchunk) issue_chunk(c + 2, (c + 2) % 3);
        CP_COMMIT();
        asm volatile("cp.async.wait_group 2;");
        __syncthreads();

        const uint32_t sA = sbase + (uint32_t)slot * STAGE_BYTES;
        const uint32_t sB = sA + A_BYTES;

        #pragma unroll
        for (int ks = 0; ks < 2; ks++) {
            uint32_t a[2][4];
            #pragma unroll
            for (int mi = 0; mi < 2; mi++)
                LDSM4(a[mi], sA + (uint32_t)((wm * 32 + mi * 16 + l15) * HROW_B + ks * 32 + koff));
            uint32_t bf[4][4];
            #pragma unroll
            for (int g = 0; g < 4; g++)
                LDSM4(bf[g], sB + (uint32_t)((wn * 64 + g * 16 + l15) * HROW_B + ks * 32 + koff));
            #pragma unroll
            for (int g = 0; g < 4; g++)
                #pragma unroll
                for (int h = 0; h < 2; h++) {
                    mma_f16(acc[0][g * 2 + h], a[0], bf[g][h], bf[g][h + 2]);
                    mma_f16(acc[1][g * 2 + h], a[1], bf[g][h], bf[g][h + 2]);
                }
        }
        __syncthreads();
        slot++; if (slot == 3) slot = 0;
    }

    #pragma unroll
    for (int mi = 0; mi < 2; mi++) {
        const int row = m0 + wm * 32 + mi * 16 + gid;
        #pragma unroll
        for (int ni = 0; ni < 8; ni++) {
            const int col = n0 + wn * 64 + ni * 8 + tig * 2;
            const float b0v = bias[col], b1v = bias[col + 1];
            float v0 = acc[mi][ni][0] + b0v;
            float v1 = acc[mi][ni][1] + b1v;
            float v2 = acc[mi][ni][2] + b0v;
            float v3 = acc[mi][ni][3] + b1v;
            if (relu) {
                v0 = fmaxf(v0, 0.f); v1 = fmaxf(v1, 0.f);
                v2 = fmaxf(v2, 0.f); v3 = fmaxf(v3, 0.f);
            }
            if (qkv_split) {
                const int buf = col >> 11, colr = col & (HS_ - 1);
                __half* Ch = (__half*)Cout + (size_t)buf * NROWS * HS_;
                *(__half2*)(Ch + (size_t)row * HS_ + colr) = __floats2half2_rn(v0, v1);
                *(__half2*)(Ch + (size_t)(row + 8) * HS_ + colr) = __floats2half2_rn(v2, v3);
            } else if (out_half) {
                __half* Ch = (__half*)Cout;
                *(__half2*)(Ch + (size_t)row * N + col) = __floats2half2_rn(v0, v1);
                *(__half2*)(Ch + (size_t)(row + 8) * N + col) = __floats2half2_rn(v2, v3);
            } else {
                float* Cf = (float*)Cout;
                float2 o01; o01.x = v0; o01.y = v1;
                float2 o23; o23.x = v2; o23.y = v3;
                *(float2*)(Cf + (size_t)row * N + col) = o01;
                *(float2*)(Cf + (size_t)(row + 8) * N + col) = o23;
            }
        }
    }
}

// ---------------------------------------------------------------------------
// Wf2 GEMM + fused LayerNorm + mask + head-major half out.
// CTA 64 (tok rows) x 256 (full FD), 8 warps 2(M)x4(N) of 32x64 each,
// 2-stage cp.async, 2 CTAs/SM. use_mask==2: rows >= NTOK are k (masked).
// ---------------------------------------------------------------------------
#define LNA_BYTES (64 * HROW_B)             // 5120
#define LNB_BYTES (256 * HROW_B)            // 20480
#define LN_STAGE  (LNA_BYTES + LNB_BYTES)   // 25600
#define LN_SMEM   (2 * LN_STAGE)            // 51200

__global__ __launch_bounds__(256, 2) void gemm_ln_kernel(
    const __half* __restrict__ A, const __half* __restrict__ BT,
    const float* __restrict__ bias, const float* __restrict__ gamma,
    const float* __restrict__ beta, const float* __restrict__ mask,
    __half* __restrict__ out, int use_mask)
{
    extern __shared__ char smraw[];
    const uint32_t sbase = smem_u32(smraw);
    float* smf = (float*)smraw;
    const int tid = threadIdx.x;
    const int wid = tid >> 5, lane = tid & 31;
    const int wm = wid & 1, wn = wid >> 1;      // 2 (M) x 4 (N)
    const int gid = lane >> 2, tig = lane & 3;
    const int m0 = blockIdx.x * 64;
    const int K = FD_;

    float acc[2][8][4];
    #pragma unroll
    for (int mi = 0; mi < 2; mi++)
        #pragma unroll
        for (int ni = 0; ni < 8; ni++)
            #pragma unroll
            for (int j = 0; j < 4; j++) acc[mi][ni][j] = 0.f;

    auto issue_chunk = [&](int c, int slot) {
        const __half* Ag = A + (size_t)m0 * K + c * 32;
        const __half* Bg = BT + c * 32;
        const uint32_t sA = sbase + (uint32_t)slot * LN_STAGE;
        const uint32_t sB = sA + LNA_BYTES;
        {   // A: 64 rows x 4 segs = 256 loads
            const int row = tid >> 2, seg = tid & 3;
            CP_ASYNC16(sA + (uint32_t)(row * HROW_B + seg * 16),
                       Ag + (size_t)row * K + seg * 8);
        }
        #pragma unroll
        for (int r = 0; r < 4; r++) {       // B: 256 rows x 4 segs
            const int idx = tid + 256 * r;
            const int row = idx >> 2, seg = idx & 3;
            CP_ASYNC16(sB + (uint32_t)(row * HROW_B + seg * 16),
                       Bg + (size_t)row * K + seg * 8);
        }
    };

    issue_chunk(0, 0); CP_COMMIT();

    const int l15 = lane & 15;
    const int koff = (lane >> 4) * 16;
    const int nchunk = K >> 5;                  // 8

    for (int c = 0; c < nchunk; c++) {
        if (c + 1 < nchunk) {
            issue_chunk(c + 1, (c + 1) & 1); CP_COMMIT();
            asm volatile("cp.async.wait_group 1;");
        } else {
            asm volatile("cp.async.wait_group 0;");
        }
        __syncthreads();

        const uint32_t sA = sbase + (uint32_t)(c & 1) * LN_STAGE;
        const uint32_t sB = sA + LNA_BYTES;

        #pragma unroll
        for (int ks = 0; ks < 2; ks++) {
            uint32_t a[2][4];
            #pragma unroll
            for (int mi = 0; mi < 2; mi++)
                LDSM4(a[mi], sA + (uint32_t)((wm * 32 + mi * 16 + l15) * HROW_B + ks * 32 + koff));
            uint32_t bf[4][4];
            #pragma unroll
            for (int g = 0; g < 4; g++)
                LDSM4(bf[g], sB + (uint32_t)((wn * 64 + g * 16 + l15) * HROW_B + ks * 32 + koff));
            #pragma unroll
            for (int mi = 0; mi < 2; mi++)
                #pragma unroll
                for (int g = 0; g < 4; g++)
                    #pragma unroll
                    for (int h = 0; h < 2; h++)
                        mma_f16(acc[mi][g * 2 + h], a[mi], bf[g][h], bf[g][h + 2]);
        }
        __syncthreads();
    }

    // Bias
    #pragma unroll
    for (int mi = 0; mi < 2; mi++)
        #pragma unroll
        for (int ni = 0; ni < 8; ni++) {
            const int col = wn * 64 + ni * 8 + tig * 2;
            acc[mi][ni][0] += bias[col];
            acc[mi][ni][1] += bias[col + 1];
            acc[mi][ni][2] += bias[col];
            acc[mi][ni][3] += bias[col + 1];
        }

    // Row stats: this thread covers rows (wm*32 + mi*16 + gid) and (+8)
    float rsum[2][2], rsq[2][2];
    #pragma unroll
    for (int mi = 0; mi < 2; mi++) {
        float slo = 0.f, qlo = 0.f, shi = 0.f, qhi = 0.f;
        #pragma unroll
        for (int ni = 0; ni < 8; ni++) {
            slo += acc[mi][ni][0] + acc[mi][ni][1];
            qlo += acc[mi][ni][0] * acc[mi][ni][0] + acc[mi][ni][1] * acc[mi][ni][1];
            shi += acc[mi][ni][2] + acc[mi][ni][3];
            qhi += acc[mi][ni][2] * acc[mi][ni][2] + acc[mi][ni][3] * acc[mi][ni][3];
        }
        #pragma unroll
        for (int o = 1; o <= 2; o <<= 1) {
            slo += __shfl_xor_sync(0xffffffffu, slo, o);
            qlo += __shfl_xor_sync(0xffffffffu, qlo, o);
            shi += __shfl_xor_sync(0xffffffffu, shi, o);
            qhi += __shfl_xor_sync(0xffffffffu, qhi, o);
        }
        rsum[mi][0] = slo; rsq[mi][0] = qlo;
        rsum[mi][1] = shi; rsq[mi][1] = qhi;
    }
    __syncthreads();   // mainloop smem reads done; reuse for stats

    if (tig == 0) {
        #pragma unroll
        for (int mi = 0; mi < 2; mi++) {
            const int rlo = wm * 32 + mi * 16 + gid;
            smf[rlo * 4 + wn] = rsum[mi][0];
            smf[256 + rlo * 4 + wn] = rsq[mi][0];
            smf[(rlo + 8) * 4 + wn] = rsum[mi][1];
            smf[256 + (rlo + 8) * 4 + wn] = rsq[mi][1];
        }
    }
    __syncthreads();

    #pragma unroll
    for (int mi = 0; mi < 2; mi++) {
        #pragma unroll
        for (int lh = 0; lh < 2; lh++) {
            const int rr = wm * 32 + mi * 16 + gid + lh * 8;
            float ts = smf[rr * 4 + 0] + smf[rr * 4 + 1] + smf[rr * 4 + 2] + smf[rr * 4 + 3];
            float tq = smf[256 + rr * 4 + 0] + smf[256 + rr * 4 + 1] +
                       smf[256 + rr * 4 + 2] + smf[256 + rr * 4 + 3];
            const float mu = ts * (1.f / FD_);
            const float var = tq * (1.f / FD_) - mu * mu;
            const float rstd = rsqrtf(var + 1e-5f);

            int tok = m0 + rr;
            const int is_k = (use_mask == 2) ? (tok >= NTOK) : 0;
            if (is_k) tok -= NTOK;
            const int h = tok & 15;
            const int bl = tok >> 4;
            const int l = bl & (L_ - 1);
            const int b = bl >> 12;
            float mscale = 1.f;
            if (use_mask == 1 || (use_mask == 2 && is_k)) mscale = 1.f + mask[bl];
            __half* orow = out + (size_t)is_k * ((size_t)NTOK * FD_) +
                           ((size_t)((b * NH_ + h)) * L_ + l) * FD_;

            #pragma unroll
            for (int ni = 0; ni < 8; ni++) {
                const int col = wn * 64 + ni * 8 + tig * 2;
                const float g0 = gamma[col], g1 = gamma[col + 1];
                const float be0 = beta[col], be1 = beta[col + 1];
                float y0 = ((acc[mi][ni][lh * 2 + 0] - mu) * rstd * g0 + be0) * mscale;
                float y1 = ((acc[mi][ni][lh * 2 + 1] - mu) * rstd * g1 + be1) * mscale;
                *(__half2*)(orow + col) = __floats2half2_rn(y0, y1);
            }
        }
    }
}

// ---------------------------------------------------------------------------
// kv via tensor cores (trans-ldmatrix), 8-way L split, coalesced fp32
// partials in [f][d] layout.
// ---------------------------------------------------------------------------
#define KV_KFROW 528
#define KV_VROW  272
#define KV_STAGE (32 * KV_KFROW + 32 * KV_VROW)
#define KV_SMEM  (2 * KV_STAGE)

__global__ __launch_bounds__(256, 1) void kv_tc_kernel(
    const __half* __restrict__ kf, const __half* __restrict__ vh,
    float* __restrict__ kvp)
{
    extern __shared__ char smraw[];
    const uint32_t sbase = smem_u32(smraw);
    const int tid = threadIdx.x;
    const int wid = tid >> 5, lane = tid & 31;
    const int wm = wid & 3, wn = wid >> 2;
    const int gid = lane >> 2, tig = lane & 3;
    const int bh = blockIdx.x, split = blockIdx.y;
    const int b = bh >> 4, h = bh & 15;
    const int k0 = split * 512;

    const __half* kfb = kf + (size_t)bh * L_ * FD_;

    float acc[4][8][4];
    #pragma unroll
    for (int mi = 0; mi < 4; mi++)
        #pragma unroll
        for (int ni = 0; ni < 8; ni++)
            #pragma unroll
            for (int j = 0; j < 4; j++) acc[mi][ni][j] = 0.f;

    auto issue_chunk = [&](int c, int slot) {
        const int l0 = k0 + c * 32;
        const uint32_t sKF = sbase + (uint32_t)slot * KV_STAGE;
        const uint32_t sV = sKF + 32 * KV_KFROW;
        #pragma unroll
        for (int r = 0; r < 4; r++) {
            const int idx = tid + 256 * r;
            const int row = idx >> 5, seg = idx & 31;
            CP_ASYNC16(sKF + (uint32_t)(row * KV_KFROW + seg * 16),
                       kfb + (size_t)(l0 + row) * FD_ + seg * 8);
        }
        #pragma unroll
        for (int r = 0; r < 2; r++) {
            const int idx = tid + 256 * r;
            const int row = idx >> 4, seg = idx & 15;
            CP_ASYNC16(sV + (uint32_t)(row * KV_VROW + seg * 16),
                       vh + ((size_t)(b * L_ + l0 + row)) * HS_ + h * HD_ + seg * 8);
        }
    };

    issue_chunk(0, 0); CP_COMMIT();

    const int quad = lane >> 3, qr = lane & 7;
    const int nchunk = 16;

    for (int c = 0; c < nchunk; c++) {
        if (c + 1 < nchunk) {
            issue_chunk(c + 1, (c + 1) & 1); CP_COMMIT();
            asm volatile("cp.async.wait_group 1;");
        } else {
            asm volatile("cp.async.wait_group 0;");
        }
        __syncthreads();

        const uint32_t sKF = sbase + (uint32_t)(c & 1) * KV_STAGE;
        const uint32_t sV = sKF + 32 * KV_KFROW;

        #pragma unroll
        for (int ks = 0; ks < 2; ks++) {
            const int lrow = ks * 16 + (quad >> 1) * 8 + qr;
            const int coff = (quad & 1) * 8;
            uint32_t a[4][4];
            #pragma unroll
            for (int mi = 0; mi < 4; mi++) {
                const int f0 = wm * 64 + mi * 16;
                LDSM4T(a[mi], sKF + (uint32_t)(lrow * KV_KFROW + (f0 + coff) * 2));
            }
            uint32_t bf[4][4];
            #pragma unroll
            for (int g = 0; g < 4; g++) {
                const int d0 = wn * 64 + g * 16;
                LDSM4T(bf[g], sV + (uint32_t)(lrow * KV_VROW + (d0 + coff) * 2));
            }
            #pragma unroll
            for (int mi = 0; mi < 4; mi++)
                #pragma unroll
                for (int g = 0; g < 4; g++)
                    #pragma unroll
                    for (int hh = 0; hh < 2; hh++)
                        mma_f16(acc[mi][g * 2 + hh], a[mi], bf[g][hh], bf[g][hh + 2]);
        }
        __syncthreads();
    }

    // Coalesced store: kvp[(split*BH+bh)][f][d], float2 per (row, col pair)
    float* outp = kvp + ((size_t)(split * BH_ + bh)) * FD_ * HD_;
    #pragma unroll
    for (int mi = 0; mi < 4; mi++) {
        const int m = wm * 64 + mi * 16 + gid;
        #pragma unroll
        for (int ni = 0; ni < 8; ni++) {
            const int n = wn * 64 + ni * 8 + tig * 2;
            float2 lo; lo.x = acc[mi][ni][0]; lo.y = acc[mi][ni][1];
            float2 hi; hi.x = acc[mi][ni][2]; hi.y = acc[mi][ni][3];
            *(float2*)(outp + (size_t)m * HD_ + n) = lo;
            *(float2*)(outp + (size_t)(m + 8) * HD_ + n) = hi;
        }
    }
}

// Reduce 8 partials [f][d] and transpose -> kvT half [bh][d][f]
__global__ __launch_bounds__(256) void kv_reduce_t_kernel(
    const float* __restrict__ kvp, __half* __restrict__ kvT)
{
    __shared__ float t[32][33];
    const int f0 = blockIdx.x * 32;      // FD/32 = 8
    const int d0 = blockIdx.y * 32;      // HD/32 = 4
    const int bh = blockIdx.z;
    const int tx = threadIdx.x & 31, ty = threadIdx.x >> 5;   // 32 x 8
    const size_t stride = (size_t)BH_ * FD_ * HD_;
    const float* base = kvp + (size_t)bh * FD_ * HD_;

    #pragma unroll
    for (int i = 0; i < 32; i += 8) {
        float s = 0.f;
        #pragma unroll
        for (int p = 0; p < 8; p++)
            s += base[p * stride + (size_t)(f0 + ty + i) * HD_ + d0 + tx];
        t[ty + i][tx] = s;
    }
    __syncthreads();
    #pragma unroll
    for (int i = 0; i < 32; i += 8)
        kvT[(size_t)bh * HD_ * FD_ + (size_t)(d0 + ty + i) * FD_ + f0 + tx] =
            __float2half_rn(t[tx][ty + i]);
}

// ---------------------------------------------------------------------------
// ksum + denom
// ---------------------------------------------------------------------------
__global__ void zero_ksum_kernel(float* __restrict__ ks)
{
    ks[blockIdx.x * FD_ + threadIdx.x] = 0.f;
}

__global__ __launch_bounds__(256) void ksum_h_kernel(
    const __half* __restrict__ kf, float* __restrict__ ks)
{
    const int bh = blockIdx.x, chunk = blockIdx.y;
    const int f = threadIdx.x;
    const __half* base = kf + (size_t)bh * L_ * FD_ + (size_t)chunk * 512 * FD_ + f;
    float acc = 0.f;
    for (int l = 0; l < 512; ++l)
        acc += __half2float(base[(size_t)l * FD_]);
    atomicAdd(&ks[bh * FD_ + f], acc);
}

__global__ __launch_bounds__(256) void denom_kernel(
    const __half* __restrict__ qf, const float* __restrict__ ks,
    float* __restrict__ den)
{
    const int wid = threadIdx.x >> 5, lane = threadIdx.x & 31;
    const int r = blockIdx.x * 8 + wid;
    const int bh = r >> 12;
    const uint4 p = *(const uint4*)(qf + (size_t)r * FD_ + lane * 8);
    const float* kp = ks + bh * FD_ + lane * 8;
    const __half2* h = (const __half2*)&p;
    float acc = 0.f;
    #pragma unroll
    for (int j = 0; j < 4; j++) {
        float2 f2 = __half22float2(h[j]);
        acc += f2.x * kp[j * 2] + f2.y * kp[j * 2 + 1];
    }
    #pragma unroll
    for (int o = 16; o; o >>= 1) acc += __shfl_down_sync(0xffffffffu, acc, o);
    if (lane == 0) den[r] = acc;
}

// ---------------------------------------------------------------------------
// attn via tensor cores (128x128, K=256) with fused denominator
// ---------------------------------------------------------------------------
__global__ __launch_bounds__(256, 2) void attn_tc_kernel(
    const __half* __restrict__ qf, const __half* __restrict__ kvT,
    const float* __restrict__ den, __half* __restrict__ out)
{
    extern __shared__ char smraw[];
    const uint32_t sbase = smem_u32(smraw);
    const int tid = threadIdx.x;
    const int wid = tid >> 5, lane = tid & 31;
    const int wm = wid & 3, wn = wid >> 2;
    const int gid = lane >> 2, tig = lane & 3;
    const int bh = blockIdx.x, l0 = blockIdx.y * 128;
    const int b = bh >> 4, h = bh & 15;
    const int K = FD_;

    const __half* A = qf + (size_t)bh * L_ * FD_ + (size_t)l0 * FD_;
    const __half* BT = kvT + (size_t)bh * HD_ * FD_;

    float acc[2][8][4];
    #pragma unroll
    for (int mi = 0; mi < 2; mi++)
        #pragma unroll
        for (int ni = 0; ni < 8; ni++)
            #pragma unroll
            for (int j = 0; j < 4; j++) acc[mi][ni][j] = 0.f;

    auto issue_chunk = [&](int c, int slot) {
        const uint32_t sA = sbase + (uint32_t)slot * STAGE_BYTES;
        const uint32_t sB = sA + A_BYTES;
        #pragma unroll
        for (int r = 0; r < 2; r++) {
            const int idx = tid + 256 * r;
            const int row = idx >> 2, seg = idx & 3;
            const uint32_t so = (uint32_t)(row * HROW_B + seg * 16);
            CP_ASYNC16(sA + so, A + (size_t)row * K + c * 32 + seg * 8);
            CP_ASYNC16(sB + so, BT + (size_t)row * K + c * 32 + seg * 8);
        }
    };

    issue_chunk(0, 0); CP_COMMIT();
    issue_chunk(1, 1); CP_COMMIT();

    const int l15 = lane & 15;
    const int koff = (lane >> 4) * 16;
    const int nchunk = K >> 5;

    int slot = 0;
    for (int c = 0; c < nchunk; c++) {
        if (c + 2 < nchunk) issue_chunk(c + 2, (c + 2) % 3);
        CP_COMMIT();
        asm volatile("cp.async.wait_group 2;");
        __syncthreads();

        const uint32_t sA = sbase + (uint32_t)slot * STAGE_BYTES;
        const uint32_t sB = sA + A_BYTES;

        #pragma unroll
        for (int ks = 0; ks < 2; ks++) {
            uint32_t a[2][4];
            #pragma unroll
            for (int mi = 0; mi < 2; mi++)
                LDSM4(a[mi], sA + (uint32_t)((wm * 32 + mi * 16 + l15) * HROW_B + ks * 32 + koff));
            uint32_t bf[4][4];
            #pragma unroll
            for (int g = 0; g < 4; g++)
                LDSM4(bf[g], sB + (uint32_t)((wn * 64 + g * 16 + l15) * HROW_B + ks * 32 + koff));
            #pragma unroll
            for (int g = 0; g < 4; g++)
                #pragma unroll
                for (int hh = 0; hh < 2; hh++) {
                    mma_f16(acc[0][g * 2 + hh], a[0], bf[g][hh], bf[g][hh + 2]);
                    mma_f16(acc[1][g * 2 + hh], a[1], bf[g][hh], bf[g][hh + 2]);
                }
        }
        __syncthreads();
        slot++; if (slot == 3) slot = 0;
    }

    #pragma unroll
    for (int mi = 0; mi < 2; mi++) {
        const int row = wm * 32 + mi * 16 + gid;
        const int llo = l0 + row, lhi = llo + 8;
        const float ilo = 1.f / (den[bh * L_ + llo] + 1e-8f);
        const float ihi = 1.f / (den[bh * L_ + lhi] + 1e-8f);
        __half* olo = out + ((size_t)(b * L_ + llo)) * HS_ + h * HD_;
        __half* ohi = out + ((size_t)(b * L_ + lhi)) * HS_ + h * HD_;
        #pragma unroll
        for (int ni = 0; ni < 8; ni++) {
            const int col = wn * 64 + ni * 8 + tig * 2;
            *(__half2*)(olo + col) = __floats2half2_rn(acc[mi][ni][0] * ilo,
                                                        acc[mi][ni][1] * ilo);
            *(__half2*)(ohi + col) = __floats2half2_rn(acc[mi][ni][2] * ihi,
                                                        acc[mi][ni][3] * ihi);
        }
    }
}

// ---------------------------------------------------------------------------
// Transposes + f2h
// ---------------------------------------------------------------------------
__global__ __launch_bounds__(256) void transpose_h_kernel(
    const float* __restrict__ src, __half* __restrict__ dst, int R, int C)
{
    __shared__ float t[32][33];
    const int bx = blockIdx.x * 32;
    const int by = blockIdx.y * 32;
    const int tx = threadIdx.x, ty = threadIdx.y;
    #pragma unroll
    for (int i = 0; i < 32; i += 8)
        t[ty + i][tx] = src[(size_t)(by + ty + i) * C + bx + tx];
    __syncthreads();
    #pragma unroll
    for (int i = 0; i < 32; i += 8)
        dst[(size_t)(bx + ty + i) * R + by + tx] = __float2half_rn(t[tx][ty + i]);
}

// 3 same-shape transposes in one launch (z selects source)
__global__ __launch_bounds__(256) void transpose3_h_kernel(
    const float* __restrict__ s0, const float* __restrict__ s1,
    const float* __restrict__ s2, __half* __restrict__ dst, int R, int C)
{
    __shared__ float t[32][33];
    const float* src = (blockIdx.z == 0) ? s0 : (blockIdx.z == 1) ? s1 : s2;
    __half* d = dst + (size_t)blockIdx.z * R * C;
    const int bx = blockIdx.x * 32;
    const int by = blockIdx.y * 32;
    const int tx = threadIdx.x, ty = threadIdx.y;
    #pragma unroll
    for (int i = 0; i < 32; i += 8)
        t[ty + i][tx] = src[(size_t)(by + ty + i) * C + bx + tx];
    __syncthreads();
    #pragma unroll
    for (int i = 0; i < 32; i += 8)
        d[(size_t)(bx + ty + i) * R + by + tx] = __float2half_rn(t[tx][ty + i]);
}

__global__ __launch_bounds__(256) void f2h_kernel(
    const float4* __restrict__ src, uint2* __restrict__ dst, int n4)
{
    const int i = blockIdx.x * 256 + threadIdx.x;
    if (i < n4) {
        float4 v = src[i];
        __half2 a = __floats2half2_rn(v.x, v.y);
        __half2 b = __floats2half2_rn(v.z, v.w);
        uint2 o;
        o.x = *(uint32_t*)&a;
        o.y = *(uint32_t*)&b;
        dst[i] = o;
    }
}

// ---------------------------------------------------------------------------
// Host launch
// ---------------------------------------------------------------------------
extern "C" void kernel_launch(void* const* d_in, const int* in_sizes, int n_in,
                              void* d_out, int out_size)
{
    (void)in_sizes; (void)n_in; (void)out_size;
    const float* X    = (const float*)d_in[0];
    const float* mask = (const float*)d_in[1];
    const float* Wq   = (const float*)d_in[2];
    const float* bq   = (const float*)d_in[3];
    const float* Wk   = (const float*)d_in[4];
    const float* bk   = (const float*)d_in[5];
    const float* Wv   = (const float*)d_in[6];
    const float* bv   = (const float*)d_in[7];
    const float* Wo   = (const float*)d_in[8];
    const float* bo   = (const float*)d_in[9];
    const float* Wf1  = (const float*)d_in[10];
    const float* bf1  = (const float*)d_in[11];
    const float* Wf2  = (const float*)d_in[12];
    const float* bf2  = (const float*)d_in[13];
    const float* ln_g = (const float*)d_in[14];
    const float* ln_b = (const float*)d_in[15];

    float* scratch = nullptr;
    cudaGetSymbolAddress((void**)&scratch, g_scratch);
    __half* Xh     = (__half*)(scratch + OFF_XH);
    __half* qkvh   = (__half*)(scratch + OFF_QKV);       // q | k | v
    __half* qh     = qkvh;
    __half* vh     = (__half*)(scratch + OFF_QKV + 16777216);
    __half* tmph   = (__half*)(scratch + OFF_TMPH);
    __half* qfh    = (__half*)(scratch + OFF_QFH);
    __half* kfh    = (__half*)(scratch + OFF_KFH);
    float*  kvp    = scratch + OFF_KVP;
    __half* kvT    = (__half*)(scratch + OFF_KVT);
    float*  ksbuf  = scratch + OFF_KSUM;
    float*  den    = scratch + OFF_DEN;
    __half* attnh  = (__half*)(scratch + OFF_ATTNH);
    __half* WqkvT  = (__half*)(scratch + OFF_WQKVT);
    __half* WoT    = (__half*)(scratch + OFF_WOT);
    __half* Wf1T   = (__half*)(scratch + OFF_WF1T);
    __half* Wf2T   = (__half*)(scratch + OFF_WF2T);
    float*  bqkv   = scratch + OFF_BQKV;

    static bool attr_set = false;
    if (!attr_set) {
        cudaFuncSetAttribute(gemm_h_kernel,
                             cudaFuncAttributeMaxDynamicSharedMemorySize, GEMM_SMEM);
        cudaFuncSetAttribute(gemm_ln_kernel,
                             cudaFuncAttributeMaxDynamicSharedMemorySize, LN_SMEM);
        cudaFuncSetAttribute(kv_tc_kernel,
                             cudaFuncAttributeMaxDynamicSharedMemorySize, KV_SMEM);
        cudaFuncSetAttribute(attn_tc_kernel,
                             cudaFuncAttributeMaxDynamicSharedMemorySize, GEMM_SMEM);
        attr_set = true;
    }

    // Combined bias [bq|bk|bv]
    cudaMemcpyAsync(bqkv,            bq, HS_ * sizeof(float), cudaMemcpyDeviceToDevice);
    cudaMemcpyAsync(bqkv + HS_,      bk, HS_ * sizeof(float), cudaMemcpyDeviceToDevice);
    cudaMemcpyAsync(bqkv + 2 * HS_,  bv, HS_ * sizeof(float), cudaMemcpyDeviceToDevice);

    dim3 t8(32, 8);
    // Weight transposes: Wq/Wk/Wv batched into one launch, then Wo/Wf1/Wf2
    transpose3_h_kernel<<<dim3(HS_/32, HS_/32, 3), t8>>>(Wq, Wk, Wv, WqkvT, HS_, HS_);
    transpose_h_kernel<<<dim3(HS_/32, HS_/32), t8>>>(Wo, WoT, HS_, HS_);
    transpose_h_kernel<<<dim3(FD_/32, HD_/32), t8>>>(Wf1, Wf1T, HD_, FD_);
    transpose_h_kernel<<<dim3(FD_/32, FD_/32), t8>>>(Wf2, Wf2T, FD_, FD_);

    f2h_kernel<<<(NROWS * HS_ / 4 + 255) / 256, 256>>>(
        (const float4*)X, (uint2*)Xh, NROWS * HS_ / 4);

    dim3 blk(256);

    // Fused QKV projection: [8192,2048] @ [6144,2048]^T -> q|k|v half buffers
    gemm_h_kernel<<<dim3(3 * HS_ / 128, NROWS / 128), blk, GEMM_SMEM>>>(
        Xh, WqkvT, bqkv, qkvh, NROWS, 3 * HS_, HS_, 0, 1, 1);

    // Fused feature gemm1 for q&k: M = 2*NTOK (q rows then k rows)
    gemm_h_kernel<<<dim3(FD_ / 128, 2 * NTOK / 128), blk, GEMM_SMEM>>>(
        qh, Wf1T, bf1, tmph, 2 * NTOK, FD_, HD_, 1, 1, 0);

    // Fused gemm2 + LN for q&k -> head-major qfh / kfh (auto mask), 64-row CTAs
    gemm_ln_kernel<<<2 * NTOK / 64, blk, LN_SMEM>>>(
        tmph, Wf2T, bf2, ln_g, ln_b, mask, qfh, 2);

    // k_sum
    zero_ksum_kernel<<<BH_, FD_>>>(ksbuf);
    ksum_h_kernel<<<dim3(BH_, 8), 256>>>(kfh, ksbuf);

    // kv (8-way L split) + transposing reduce -> kvT half [bh][d][f]
    kv_tc_kernel<<<dim3(BH_, 8), blk, KV_SMEM>>>(kfh, vh, kvp);
    kv_reduce_t_kernel<<<dim3(FD_/32, HD_/32, BH_), 256>>>(kvp, kvT);

    // denom
    denom_kernel<<<NTOK / 8, 256>>>(qfh, ksbuf, den);

    // attn -> tok-major half
    attn_tc_kernel<<<dim3(BH_, L_ / 128), blk, GEMM_SMEM>>>(qfh, kvT, den, attnh);

    // output projection (fp32 to d_out)
    gemm_h_kernel<<<dim3(HS_ / 128, NROWS / 128), blk, GEMM_SMEM>>>(
        attnh, WoT, bo, (float*)d_out, NROWS, HS_, HS_, 0, 0, 0);
}

// round 17
// speedup vs baseline: 1.2751x; 1.1012x over previous
#include <cuda_runtime.h>
#include <cuda_fp16.h>
#include <cstdint>

// Problem constants
#define B_  2
#define L_  4096
#define HS_ 2048
#define NH_ 16
#define HD_ 128
#define FD_ 256
#define NROWS (B_*L_)            // 8192
#define NTOK  (B_*L_*NH_)        // 131072
#define BH_   (B_*NH_)           // 32

// Scratch layout (float units)
#define OFF_XH    ((size_t)0)                        // 8388608
#define OFF_QKV   ((size_t)8388608)                  // q|k|v each 8388608
#define OFF_TMPH  ((size_t)33554432)                 // 33554432 (262144x256 half)
#define OFF_QFH   ((size_t)67108864)                 // 16777216
#define OFF_KFH   ((size_t)83886080)                 // 16777216
#define OFF_KVP   ((size_t)100663296)                // 8388608
#define OFF_KVT   ((size_t)109051904)                // 524288
#define OFF_KSUM  ((size_t)109576192)                // 8192
#define OFF_DEN   ((size_t)109584384)                // 131072
#define OFF_ATTNH ((size_t)109715456)                // 8388608
#define OFF_WQKVT ((size_t)118104064)                // 6291456 (6144x2048 half)
#define OFF_WOT   ((size_t)124395520)                // 2097152
#define OFF_WF1T  ((size_t)126492672)                // 16384
#define OFF_WF2T  ((size_t)126509056)                // 32768
#define OFF_BQKV  ((size_t)126541824)                // 6144
#define SCRATCH_TOTAL ((size_t)126548992)

__device__ float g_scratch[SCRATCH_TOTAL];

// ---------------------------------------------------------------------------
// Helpers
// ---------------------------------------------------------------------------
__device__ __forceinline__ uint32_t smem_u32(const void* p) {
    uint32_t a;
    asm("{ .reg .u64 t; cvta.to.shared.u64 t, %1; cvt.u32.u64 %0, t; }"
        : "=r"(a) : "l"(p));
    return a;
}

#define CP_ASYNC16(saddr, gaddr) \
    asm volatile("cp.async.cg.shared.global [%0], [%1], 16;" \
                 :: "r"(saddr), "l"(gaddr))
#define CP_COMMIT() asm volatile("cp.async.commit_group;")

#define LDSM4(r, addr) \
    asm volatile("ldmatrix.sync.aligned.m8n8.x4.shared.b16 {%0,%1,%2,%3}, [%4];" \
                 : "=r"((r)[0]), "=r"((r)[1]), "=r"((r)[2]), "=r"((r)[3]) \
                 : "r"(addr))

#define LDSM4T(r, addr) \
    asm volatile("ldmatrix.sync.aligned.m8n8.x4.trans.shared.b16 {%0,%1,%2,%3}, [%4];" \
                 : "=r"((r)[0]), "=r"((r)[1]), "=r"((r)[2]), "=r"((r)[3]) \
                 : "r"(addr))

__device__ __forceinline__ void mma_f16(float* d, const uint32_t* a,
                                        uint32_t b0, uint32_t b1) {
    asm volatile(
        "mma.sync.aligned.m16n8k16.row.col.f32.f16.f16.f32 "
        "{%0,%1,%2,%3}, {%4,%5,%6,%7}, {%8,%9}, {%0,%1,%2,%3};"
        : "+f"(d[0]), "+f"(d[1]), "+f"(d[2]), "+f"(d[3])
        : "r"(a[0]), "r"(a[1]), "r"(a[2]), "r"(a[3]), "r"(b0), "r"(b1));
}

#define HROW_B   80

// ---------------------------------------------------------------------------
// fp16 tensor GEMM, BK=64 chunks: C = A[M,K]@BT[N,K]^T + bias.
// CTA 128x128, 8 warps (32x64), 3-stage cp.async of 64-k chunks (144B rows,
// conflict-free ldmatrix), 2 CTAs/SM. K must be a multiple of 64.
// qkv_split: route output columns (N=6144) into 3 [NROWS,HS] half buffers.
// ---------------------------------------------------------------------------
#define HR64      144
#define G64_AB    (128 * HR64)            // 18432
#define G64_STAGE (2 * G64_AB)            // 36864
#define G64_SMEM  (3 * G64_STAGE)         // 110592

__global__ __launch_bounds__(256, 2) void gemm_h_kernel(
    const __half* __restrict__ A, const __half* __restrict__ BT,
    const float* __restrict__ bias, void* __restrict__ Cout,
    int M, int N, int K, int relu, int out_half, int qkv_split)
{
    extern __shared__ char smraw[];
    const uint32_t sbase = smem_u32(smraw);
    const int tid = threadIdx.x;
    const int wid = tid >> 5, lane = tid & 31;
    const int wm = wid & 3, wn = wid >> 2;
    const int gid = lane >> 2, tig = lane & 3;
    const int n0 = blockIdx.x * 128, m0 = blockIdx.y * 128;

    float acc[2][8][4];
    #pragma unroll
    for (int mi = 0; mi < 2; mi++)
        #pragma unroll
        for (int ni = 0; ni < 8; ni++)
            #pragma unroll
            for (int j = 0; j < 4; j++) acc[mi][ni][j] = 0.f;

    const int nchunk = K >> 6;

    auto issue_chunk = [&](int c, int slot) {
        const __half* Ag = A + (size_t)m0 * K + c * 64;
        const __half* Bg = BT + (size_t)n0 * K + c * 64;
        const uint32_t sA = sbase + (uint32_t)slot * G64_STAGE;
        const uint32_t sB = sA + G64_AB;
        #pragma unroll
        for (int r = 0; r < 4; r++) {
            const int idx = tid + 256 * r;            // 1024: 128 rows x 8 segs
            const int row = idx >> 3, seg = idx & 7;
            const uint32_t so = (uint32_t)(row * HR64 + seg * 16);
            CP_ASYNC16(sA + so, Ag + (size_t)row * K + seg * 8);
            CP_ASYNC16(sB + so, Bg + (size_t)row * K + seg * 8);
        }
    };

    issue_chunk(0, 0); CP_COMMIT();
    if (nchunk > 1) issue_chunk(1, 1);
    CP_COMMIT();

    const int l15 = lane & 15;
    const int khalf = (lane >> 4) * 16;

    int slot = 0;
    for (int c = 0; c < nchunk; c++) {
        if (c + 2 < nchunk) issue_chunk(c + 2, (c + 2) % 3);
        CP_COMMIT();
        asm volatile("cp.async.wait_group 2;");
        __syncthreads();

        const uint32_t sA = sbase + (uint32_t)slot * G64_STAGE;
        const uint32_t sB = sA + G64_AB;

        #pragma unroll
        for (int ks = 0; ks < 4; ks++) {
            const int koff = ks * 32 + khalf;
            uint32_t a[2][4];
            #pragma unroll
            for (int mi = 0; mi < 2; mi++)
                LDSM4(a[mi], sA + (uint32_t)((wm * 32 + mi * 16 + l15) * HR64 + koff));
            uint32_t bf[4][4];
            #pragma unroll
            for (int g = 0; g < 4; g++)
                LDSM4(bf[g], sB + (uint32_t)((wn * 64 + g * 16 + l15) * HR64 + koff));
            #pragma unroll
            for (int g = 0; g < 4; g++)
                #pragma unroll
                for (int h = 0; h < 2; h++) {
                    mma_f16(acc[0][g * 2 + h], a[0], bf[g][h], bf[g][h + 2]);
                    mma_f16(acc[1][g * 2 + h], a[1], bf[g][h], bf[g][h + 2]);
                }
        }
        __syncthreads();
        slot++; if (slot == 3) slot = 0;
    }

    #pragma unroll
    for (int mi = 0; mi < 2; mi++) {
        const int row = m0 + wm * 32 + mi * 16 + gid;
        #pragma unroll
        for (int ni = 0; ni < 8; ni++) {
            const int col = n0 + wn * 64 + ni * 8 + tig * 2;
            const float b0v = bias[col], b1v = bias[col + 1];
            float v0 = acc[mi][ni][0] + b0v;
            float v1 = acc[mi][ni][1] + b1v;
            float v2 = acc[mi][ni][2] + b0v;
            float v3 = acc[mi][ni][3] + b1v;
            if (relu) {
                v0 = fmaxf(v0, 0.f); v1 = fmaxf(v1, 0.f);
                v2 = fmaxf(v2, 0.f); v3 = fmaxf(v3, 0.f);
            }
            if (qkv_split) {
                const int buf = col >> 11, colr = col & (HS_ - 1);
                __half* Ch = (__half*)Cout + (size_t)buf * NROWS * HS_;
                *(__half2*)(Ch + (size_t)row * HS_ + colr) = __floats2half2_rn(v0, v1);
                *(__half2*)(Ch + (size_t)(row + 8) * HS_ + colr) = __floats2half2_rn(v2, v3);
            } else if (out_half) {
                __half* Ch = (__half*)Cout;
                *(__half2*)(Ch + (size_t)row * N + col) = __floats2half2_rn(v0, v1);
                *(__half2*)(Ch + (size_t)(row + 8) * N + col) = __floats2half2_rn(v2, v3);
            } else {
                float* Cf = (float*)Cout;
                float2 o01; o01.x = v0; o01.y = v1;
                float2 o23; o23.x = v2; o23.y = v3;
                *(float2*)(Cf + (size_t)row * N + col) = o01;
                *(float2*)(Cf + (size_t)(row + 8) * N + col) = o23;
            }
        }
    }
}

// ---------------------------------------------------------------------------
// Wf2 GEMM + fused LayerNorm + mask + head-major half out.
// CTA 64 (tok rows) x 256 (full FD), 8 warps 2(M)x4(N) of 32x64 each,
// 2-stage cp.async, 2 CTAs/SM. use_mask==2: rows >= NTOK are k (masked).
// ---------------------------------------------------------------------------
#define LNA_BYTES (64 * HROW_B)             // 5120
#define LNB_BYTES (256 * HROW_B)            // 20480
#define LN_STAGE  (LNA_BYTES + LNB_BYTES)   // 25600
#define LN_SMEM   (2 * LN_STAGE)            // 51200

__global__ __launch_bounds__(256, 2) void gemm_ln_kernel(
    const __half* __restrict__ A, const __half* __restrict__ BT,
    const float* __restrict__ bias, const float* __restrict__ gamma,
    const float* __restrict__ beta, const float* __restrict__ mask,
    __half* __restrict__ out, int use_mask)
{
    extern __shared__ char smraw[];
    const uint32_t sbase = smem_u32(smraw);
    float* smf = (float*)smraw;
    const int tid = threadIdx.x;
    const int wid = tid >> 5, lane = tid & 31;
    const int wm = wid & 1, wn = wid >> 1;      // 2 (M) x 4 (N)
    const int gid = lane >> 2, tig = lane & 3;
    const int m0 = blockIdx.x * 64;
    const int K = FD_;

    float acc[2][8][4];
    #pragma unroll
    for (int mi = 0; mi < 2; mi++)
        #pragma unroll
        for (int ni = 0; ni < 8; ni++)
            #pragma unroll
            for (int j = 0; j < 4; j++) acc[mi][ni][j] = 0.f;

    auto issue_chunk = [&](int c, int slot) {
        const __half* Ag = A + (size_t)m0 * K + c * 32;
        const __half* Bg = BT + c * 32;
        const uint32_t sA = sbase + (uint32_t)slot * LN_STAGE;
        const uint32_t sB = sA + LNA_BYTES;
        {   // A: 64 rows x 4 segs = 256 loads
            const int row = tid >> 2, seg = tid & 3;
            CP_ASYNC16(sA + (uint32_t)(row * HROW_B + seg * 16),
                       Ag + (size_t)row * K + seg * 8);
        }
        #pragma unroll
        for (int r = 0; r < 4; r++) {       // B: 256 rows x 4 segs
            const int idx = tid + 256 * r;
            const int row = idx >> 2, seg = idx & 3;
            CP_ASYNC16(sB + (uint32_t)(row * HROW_B + seg * 16),
                       Bg + (size_t)row * K + seg * 8);
        }
    };

    issue_chunk(0, 0); CP_COMMIT();

    const int l15 = lane & 15;
    const int koff = (lane >> 4) * 16;
    const int nchunk = K >> 5;                  // 8

    for (int c = 0; c < nchunk; c++) {
        if (c + 1 < nchunk) {
            issue_chunk(c + 1, (c + 1) & 1); CP_COMMIT();
            asm volatile("cp.async.wait_group 1;");
        } else {
            asm volatile("cp.async.wait_group 0;");
        }
        __syncthreads();

        const uint32_t sA = sbase + (uint32_t)(c & 1) * LN_STAGE;
        const uint32_t sB = sA + LNA_BYTES;

        #pragma unroll
        for (int ks = 0; ks < 2; ks++) {
            uint32_t a[2][4];
            #pragma unroll
            for (int mi = 0; mi < 2; mi++)
                LDSM4(a[mi], sA + (uint32_t)((wm * 32 + mi * 16 + l15) * HROW_B + ks * 32 + koff));
            uint32_t bf[4][4];
            #pragma unroll
            for (int g = 0; g < 4; g++)
                LDSM4(bf[g], sB + (uint32_t)((wn * 64 + g * 16 + l15) * HROW_B + ks * 32 + koff));
            #pragma unroll
            for (int mi = 0; mi < 2; mi++)
                #pragma unroll
                for (int g = 0; g < 4; g++)
                    #pragma unroll
                    for (int h = 0; h < 2; h++)
                        mma_f16(acc[mi][g * 2 + h], a[mi], bf[g][h], bf[g][h + 2]);
        }
        __syncthreads();
    }

    // Bias
    #pragma unroll
    for (int mi = 0; mi < 2; mi++)
        #pragma unroll
        for (int ni = 0; ni < 8; ni++) {
            const int col = wn * 64 + ni * 8 + tig * 2;
            acc[mi][ni][0] += bias[col];
            acc[mi][ni][1] += bias[col + 1];
            acc[mi][ni][2] += bias[col];
            acc[mi][ni][3] += bias[col + 1];
        }

    // Row stats
    float rsum[2][2], rsq[2][2];
    #pragma unroll
    for (int mi = 0; mi < 2; mi++) {
        float slo = 0.f, qlo = 0.f, shi = 0.f, qhi = 0.f;
        #pragma unroll
        for (int ni = 0; ni < 8; ni++) {
            slo += acc[mi][ni][0] + acc[mi][ni][1];
            qlo += acc[mi][ni][0] * acc[mi][ni][0] + acc[mi][ni][1] * acc[mi][ni][1];
            shi += acc[mi][ni][2] + acc[mi][ni][3];
            qhi += acc[mi][ni][2] * acc[mi][ni][2] + acc[mi][ni][3] * acc[mi][ni][3];
        }
        #pragma unroll
        for (int o = 1; o <= 2; o <<= 1) {
            slo += __shfl_xor_sync(0xffffffffu, slo, o);
            qlo += __shfl_xor_sync(0xffffffffu, qlo, o);
            shi += __shfl_xor_sync(0xffffffffu, shi, o);
            qhi += __shfl_xor_sync(0xffffffffu, qhi, o);
        }
        rsum[mi][0] = slo; rsq[mi][0] = qlo;
        rsum[mi][1] = shi; rsq[mi][1] = qhi;
    }
    __syncthreads();

    if (tig == 0) {
        #pragma unroll
        for (int mi = 0; mi < 2; mi++) {
            const int rlo = wm * 32 + mi * 16 + gid;
            smf[rlo * 4 + wn] = rsum[mi][0];
            smf[256 + rlo * 4 + wn] = rsq[mi][0];
            smf[(rlo + 8) * 4 + wn] = rsum[mi][1];
            smf[256 + (rlo + 8) * 4 + wn] = rsq[mi][1];
        }
    }
    __syncthreads();

    #pragma unroll
    for (int mi = 0; mi < 2; mi++) {
        #pragma unroll
        for (int lh = 0; lh < 2; lh++) {
            const int rr = wm * 32 + mi * 16 + gid + lh * 8;
            float ts = smf[rr * 4 + 0] + smf[rr * 4 + 1] + smf[rr * 4 + 2] + smf[rr * 4 + 3];
            float tq = smf[256 + rr * 4 + 0] + smf[256 + rr * 4 + 1] +
                       smf[256 + rr * 4 + 2] + smf[256 + rr * 4 + 3];
            const float mu = ts * (1.f / FD_);
            const float var = tq * (1.f / FD_) - mu * mu;
            const float rstd = rsqrtf(var + 1e-5f);

            int tok = m0 + rr;
            const int is_k = (use_mask == 2) ? (tok >= NTOK) : 0;
            if (is_k) tok -= NTOK;
            const int h = tok & 15;
            const int bl = tok >> 4;
            const int l = bl & (L_ - 1);
            const int b = bl >> 12;
            float mscale = 1.f;
            if (use_mask == 1 || (use_mask == 2 && is_k)) mscale = 1.f + mask[bl];
            __half* orow = out + (size_t)is_k * ((size_t)NTOK * FD_) +
                           ((size_t)((b * NH_ + h)) * L_ + l) * FD_;

            #pragma unroll
            for (int ni = 0; ni < 8; ni++) {
                const int col = wn * 64 + ni * 8 + tig * 2;
                const float g0 = gamma[col], g1 = gamma[col + 1];
                const float be0 = beta[col], be1 = beta[col + 1];
                float y0 = ((acc[mi][ni][lh * 2 + 0] - mu) * rstd * g0 + be0) * mscale;
                float y1 = ((acc[mi][ni][lh * 2 + 1] - mu) * rstd * g1 + be1) * mscale;
                *(__half2*)(orow + col) = __floats2half2_rn(y0, y1);
            }
        }
    }
}

// ---------------------------------------------------------------------------
// kv via tensor cores (trans-ldmatrix), 8-way L split, coalesced fp32
// partials in [f][d] layout.
// ---------------------------------------------------------------------------
#define KV_KFROW 528
#define KV_VROW  272
#define KV_STAGE (32 * KV_KFROW + 32 * KV_VROW)
#define KV_SMEM  (2 * KV_STAGE)

__global__ __launch_bounds__(256, 1) void kv_tc_kernel(
    const __half* __restrict__ kf, const __half* __restrict__ vh,
    float* __restrict__ kvp)
{
    extern __shared__ char smraw[];
    const uint32_t sbase = smem_u32(smraw);
    const int tid = threadIdx.x;
    const int wid = tid >> 5, lane = tid & 31;
    const int wm = wid & 3, wn = wid >> 2;
    const int gid = lane >> 2, tig = lane & 3;
    const int bh = blockIdx.x, split = blockIdx.y;
    const int b = bh >> 4, h = bh & 15;
    const int k0 = split * 512;

    const __half* kfb = kf + (size_t)bh * L_ * FD_;

    float acc[4][8][4];
    #pragma unroll
    for (int mi = 0; mi < 4; mi++)
        #pragma unroll
        for (int ni = 0; ni < 8; ni++)
            #pragma unroll
            for (int j = 0; j < 4; j++) acc[mi][ni][j] = 0.f;

    auto issue_chunk = [&](int c, int slot) {
        const int l0 = k0 + c * 32;
        const uint32_t sKF = sbase + (uint32_t)slot * KV_STAGE;
        const uint32_t sV = sKF + 32 * KV_KFROW;
        #pragma unroll
        for (int r = 0; r < 4; r++) {
            const int idx = tid + 256 * r;
            const int row = idx >> 5, seg = idx & 31;
            CP_ASYNC16(sKF + (uint32_t)(row * KV_KFROW + seg * 16),
                       kfb + (size_t)(l0 + row) * FD_ + seg * 8);
        }
        #pragma unroll
        for (int r = 0; r < 2; r++) {
            const int idx = tid + 256 * r;
            const int row = idx >> 4, seg = idx & 15;
            CP_ASYNC16(sV + (uint32_t)(row * KV_VROW + seg * 16),
                       vh + ((size_t)(b * L_ + l0 + row)) * HS_ + h * HD_ + seg * 8);
        }
    };

    issue_chunk(0, 0); CP_COMMIT();

    const int quad = lane >> 3, qr = lane & 7;
    const int nchunk = 16;

    for (int c = 0; c < nchunk; c++) {
        if (c + 1 < nchunk) {
            issue_chunk(c + 1, (c + 1) & 1); CP_COMMIT();
            asm volatile("cp.async.wait_group 1;");
        } else {
            asm volatile("cp.async.wait_group 0;");
        }
        __syncthreads();

        const uint32_t sKF = sbase + (uint32_t)(c & 1) * KV_STAGE;
        const uint32_t sV = sKF + 32 * KV_KFROW;

        #pragma unroll
        for (int ks = 0; ks < 2; ks++) {
            const int lrow = ks * 16 + (quad >> 1) * 8 + qr;
            const int coff = (quad & 1) * 8;
            uint32_t a[4][4];
            #pragma unroll
            for (int mi = 0; mi < 4; mi++) {
                const int f0 = wm * 64 + mi * 16;
                LDSM4T(a[mi], sKF + (uint32_t)(lrow * KV_KFROW + (f0 + coff) * 2));
            }
            uint32_t bf[4][4];
            #pragma unroll
            for (int g = 0; g < 4; g++) {
                const int d0 = wn * 64 + g * 16;
                LDSM4T(bf[g], sV + (uint32_t)(lrow * KV_VROW + (d0 + coff) * 2));
            }
            #pragma unroll
            for (int mi = 0; mi < 4; mi++)
                #pragma unroll
                for (int g = 0; g < 4; g++)
                    #pragma unroll
                    for (int hh = 0; hh < 2; hh++)
                        mma_f16(acc[mi][g * 2 + hh], a[mi], bf[g][hh], bf[g][hh + 2]);
        }
        __syncthreads();
    }

    // Coalesced store: kvp[(split*BH+bh)][f][d]
    float* outp = kvp + ((size_t)(split * BH_ + bh)) * FD_ * HD_;
    #pragma unroll
    for (int mi = 0; mi < 4; mi++) {
        const int m = wm * 64 + mi * 16 + gid;
        #pragma unroll
        for (int ni = 0; ni < 8; ni++) {
            const int n = wn * 64 + ni * 8 + tig * 2;
            float2 lo; lo.x = acc[mi][ni][0]; lo.y = acc[mi][ni][1];
            float2 hi; hi.x = acc[mi][ni][2]; hi.y = acc[mi][ni][3];
            *(float2*)(outp + (size_t)m * HD_ + n) = lo;
            *(float2*)(outp + (size_t)(m + 8) * HD_ + n) = hi;
        }
    }
}

// Reduce 8 partials [f][d] and transpose -> kvT half [bh][d][f]
__global__ __launch_bounds__(256) void kv_reduce_t_kernel(
    const float* __restrict__ kvp, __half* __restrict__ kvT)
{
    __shared__ float t[32][33];
    const int f0 = blockIdx.x * 32;
    const int d0 = blockIdx.y * 32;
    const int bh = blockIdx.z;
    const int tx = threadIdx.x & 31, ty = threadIdx.x >> 5;
    const size_t stride = (size_t)BH_ * FD_ * HD_;
    const float* base = kvp + (size_t)bh * FD_ * HD_;

    #pragma unroll
    for (int i = 0; i < 32; i += 8) {
        float s = 0.f;
        #pragma unroll
        for (int p = 0; p < 8; p++)
            s += base[p * stride + (size_t)(f0 + ty + i) * HD_ + d0 + tx];
        t[ty + i][tx] = s;
    }
    __syncthreads();
    #pragma unroll
    for (int i = 0; i < 32; i += 8)
        kvT[(size_t)bh * HD_ * FD_ + (size_t)(d0 + ty + i) * FD_ + f0 + tx] =
            __float2half_rn(t[tx][ty + i]);
}

// ---------------------------------------------------------------------------
// ksum + denom
// ---------------------------------------------------------------------------
__global__ void zero_ksum_kernel(float* __restrict__ ks)
{
    ks[blockIdx.x * FD_ + threadIdx.x] = 0.f;
}

__global__ __launch_bounds__(256) void ksum_h_kernel(
    const __half* __restrict__ kf, float* __restrict__ ks)
{
    const int bh = blockIdx.x, chunk = blockIdx.y;
    const int f = threadIdx.x;
    const __half* base = kf + (size_t)bh * L_ * FD_ + (size_t)chunk * 512 * FD_ + f;
    float acc = 0.f;
    for (int l = 0; l < 512; ++l)
        acc += __half2float(base[(size_t)l * FD_]);
    atomicAdd(&ks[bh * FD_ + f], acc);
}

__global__ __launch_bounds__(256) void denom_kernel(
    const __half* __restrict__ qf, const float* __restrict__ ks,
    float* __restrict__ den)
{
    const int wid = threadIdx.x >> 5, lane = threadIdx.x & 31;
    const int r = blockIdx.x * 8 + wid;
    const int bh = r >> 12;
    const uint4 p = *(const uint4*)(qf + (size_t)r * FD_ + lane * 8);
    const float* kp = ks + bh * FD_ + lane * 8;
    const __half2* h = (const __half2*)&p;
    float acc = 0.f;
    #pragma unroll
    for (int j = 0; j < 4; j++) {
        float2 f2 = __half22float2(h[j]);
        acc += f2.x * kp[j * 2] + f2.y * kp[j * 2 + 1];
    }
    #pragma unroll
    for (int o = 16; o; o >>= 1) acc += __shfl_down_sync(0xffffffffu, acc, o);
    if (lane == 0) den[r] = acc;
}

// ---------------------------------------------------------------------------
// attn via tensor cores (128x128, K=256) with fused denominator
// ---------------------------------------------------------------------------
#define A_BYTES  (128 * HROW_B)
#define STAGE_BYTES (2 * A_BYTES)
#define GEMM_SMEM (3 * STAGE_BYTES)

__global__ __launch_bounds__(256, 2) void attn_tc_kernel(
    const __half* __restrict__ qf, const __half* __restrict__ kvT,
    const float* __restrict__ den, __half* __restrict__ out)
{
    extern __shared__ char smraw[];
    const uint32_t sbase = smem_u32(smraw);
    const int tid = threadIdx.x;
    const int wid = tid >> 5, lane = tid & 31;
    const int wm = wid & 3, wn = wid >> 2;
    const int gid = lane >> 2, tig = lane & 3;
    const int bh = blockIdx.x, l0 = blockIdx.y * 128;
    const int b = bh >> 4, h = bh & 15;
    const int K = FD_;

    const __half* A = qf + (size_t)bh * L_ * FD_ + (size_t)l0 * FD_;
    const __half* BT = kvT + (size_t)bh * HD_ * FD_;

    float acc[2][8][4];
    #pragma unroll
    for (int mi = 0; mi < 2; mi++)
        #pragma unroll
        for (int ni = 0; ni < 8; ni++)
            #pragma unroll
            for (int j = 0; j < 4; j++) acc[mi][ni][j] = 0.f;

    auto issue_chunk = [&](int c, int slot) {
        const uint32_t sA = sbase + (uint32_t)slot * STAGE_BYTES;
        const uint32_t sB = sA + A_BYTES;
        #pragma unroll
        for (int r = 0; r < 2; r++) {
            const int idx = tid + 256 * r;
            const int row = idx >> 2, seg = idx & 3;
            const uint32_t so = (uint32_t)(row * HROW_B + seg * 16);
            CP_ASYNC16(sA + so, A + (size_t)row * K + c * 32 + seg * 8);
            CP_ASYNC16(sB + so, BT + (size_t)row * K + c * 32 + seg * 8);
        }
    };

    issue_chunk(0, 0); CP_COMMIT();
    issue_chunk(1, 1); CP_COMMIT();

    const int l15 = lane & 15;
    const int koff = (lane >> 4) * 16;
    const int nchunk = K >> 5;

    int slot = 0;
    for (int c = 0; c < nchunk; c++) {
        if (c + 2 < nchunk) issue_chunk(c + 2, (c + 2) % 3);
        CP_COMMIT();
        asm volatile("cp.async.wait_group 2;");
        __syncthreads();

        const uint32_t sA = sbase + (uint32_t)slot * STAGE_BYTES;
        const uint32_t sB = sA + A_BYTES;

        #pragma unroll
        for (int ks = 0; ks < 2; ks++) {
            uint32_t a[2][4];
            #pragma unroll
            for (int mi = 0; mi < 2; mi++)
                LDSM4(a[mi], sA + (uint32_t)((wm * 32 + mi * 16 + l15) * HROW_B + ks * 32 + koff));
            uint32_t bf[4][4];
            #pragma unroll
            for (int g = 0; g < 4; g++)
                LDSM4(bf[g], sB + (uint32_t)((wn * 64 + g * 16 + l15) * HROW_B + ks * 32 + koff));
            #pragma unroll
            for (int g = 0; g < 4; g++)
                #pragma unroll
                for (int hh = 0; hh < 2; hh++) {
                    mma_f16(acc[0][g * 2 + hh], a[0], bf[g][hh], bf[g][hh + 2]);
                    mma_f16(acc[1][g * 2 + hh], a[1], bf[g][hh], bf[g][hh + 2]);
                }
        }
        __syncthreads();
        slot++; if (slot == 3) slot = 0;
    }

    #pragma unroll
    for (int mi = 0; mi < 2; mi++) {
        const int row = wm * 32 + mi * 16 + gid;
        const int llo = l0 + row, lhi = llo + 8;
        const float ilo = 1.f / (den[bh * L_ + llo] + 1e-8f);
        const float ihi = 1.f / (den[bh * L_ + lhi] + 1e-8f);
        __half* olo = out + ((size_t)(b * L_ + llo)) * HS_ + h * HD_;
        __half* ohi = out + ((size_t)(b * L_ + lhi)) * HS_ + h * HD_;
        #pragma unroll
        for (int ni = 0; ni < 8; ni++) {
            const int col = wn * 64 + ni * 8 + tig * 2;
            *(__half2*)(olo + col) = __floats2half2_rn(acc[mi][ni][0] * ilo,
                                                        acc[mi][ni][1] * ilo);
            *(__half2*)(ohi + col) = __floats2half2_rn(acc[mi][ni][2] * ihi,
                                                        acc[mi][ni][3] * ihi);
        }
    }
}

// ---------------------------------------------------------------------------
// Transposes + f2h
// ---------------------------------------------------------------------------
__global__ __launch_bounds__(256) void transpose_h_kernel(
    const float* __restrict__ src, __half* __restrict__ dst, int R, int C)
{
    __shared__ float t[32][33];
    const int bx = blockIdx.x * 32;
    const int by = blockIdx.y * 32;
    const int tx = threadIdx.x, ty = threadIdx.y;
    #pragma unroll
    for (int i = 0; i < 32; i += 8)
        t[ty + i][tx] = src[(size_t)(by + ty + i) * C + bx + tx];
    __syncthreads();
    #pragma unroll
    for (int i = 0; i < 32; i += 8)
        dst[(size_t)(bx + ty + i) * R + by + tx] = __float2half_rn(t[tx][ty + i]);
}

// 3 same-shape transposes in one launch (z selects source)
__global__ __launch_bounds__(256) void transpose3_h_kernel(
    const float* __restrict__ s0, const float* __restrict__ s1,
    const float* __restrict__ s2, __half* __restrict__ dst, int R, int C)
{
    __shared__ float t[32][33];
    const float* src = (blockIdx.z == 0) ? s0 : (blockIdx.z == 1) ? s1 : s2;
    __half* d = dst + (size_t)blockIdx.z * R * C;
    const int bx = blockIdx.x * 32;
    const int by = blockIdx.y * 32;
    const int tx = threadIdx.x, ty = threadIdx.y;
    #pragma unroll
    for (int i = 0; i < 32; i += 8)
        t[ty + i][tx] = src[(size_t)(by + ty + i) * C + bx + tx];
    __syncthreads();
    #pragma unroll
    for (int i = 0; i < 32; i += 8)
        d[(size_t)(bx + ty + i) * R + by + tx] = __float2half_rn(t[tx][ty + i]);
}

__global__ __launch_bounds__(256) void f2h_kernel(
    const float4* __restrict__ src, uint2* __restrict__ dst, int n4)
{
    const int i = blockIdx.x * 256 + threadIdx.x;
    if (i < n4) {
        float4 v = src[i];
        __half2 a = __floats2half2_rn(v.x, v.y);
        __half2 b = __floats2half2_rn(v.z, v.w);
        uint2 o;
        o.x = *(uint32_t*)&a;
        o.y = *(uint32_t*)&b;
        dst[i] = o;
    }
}

// ---------------------------------------------------------------------------
// Host launch
// ---------------------------------------------------------------------------
extern "C" void kernel_launch(void* const* d_in, const int* in_sizes, int n_in,
                              void* d_out, int out_size)
{
    (void)in_sizes; (void)n_in; (void)out_size;
    const float* X    = (const float*)d_in[0];
    const float* mask = (const float*)d_in[1];
    const float* Wq   = (const float*)d_in[2];
    const float* bq   = (const float*)d_in[3];
    const float* Wk   = (const float*)d_in[4];
    const float* bk   = (const float*)d_in[5];
    const float* Wv   = (const float*)d_in[6];
    const float* bv   = (const float*)d_in[7];
    const float* Wo   = (const float*)d_in[8];
    const float* bo   = (const float*)d_in[9];
    const float* Wf1  = (const float*)d_in[10];
    const float* bf1  = (const float*)d_in[11];
    const float* Wf2  = (const float*)d_in[12];
    const float* bf2  = (const float*)d_in[13];
    const float* ln_g = (const float*)d_in[14];
    const float* ln_b = (const float*)d_in[15];

    float* scratch = nullptr;
    cudaGetSymbolAddress((void**)&scratch, g_scratch);
    __half* Xh     = (__half*)(scratch + OFF_XH);
    __half* qkvh   = (__half*)(scratch + OFF_QKV);       // q | k | v
    __half* qh     = qkvh;
    __half* vh     = (__half*)(scratch + OFF_QKV + 16777216);
    __half* tmph   = (__half*)(scratch + OFF_TMPH);
    __half* qfh    = (__half*)(scratch + OFF_QFH);
    __half* kfh    = (__half*)(scratch + OFF_KFH);
    float*  kvp    = scratch + OFF_KVP;
    __half* kvT    = (__half*)(scratch + OFF_KVT);
    float*  ksbuf  = scratch + OFF_KSUM;
    float*  den    = scratch + OFF_DEN;
    __half* attnh  = (__half*)(scratch + OFF_ATTNH);
    __half* WqkvT  = (__half*)(scratch + OFF_WQKVT);
    __half* WoT    = (__half*)(scratch + OFF_WOT);
    __half* Wf1T   = (__half*)(scratch + OFF_WF1T);
    __half* Wf2T   = (__half*)(scratch + OFF_WF2T);
    float*  bqkv   = scratch + OFF_BQKV;

    static bool attr_set = false;
    if (!attr_set) {
        cudaFuncSetAttribute(gemm_h_kernel,
                             cudaFuncAttributeMaxDynamicSharedMemorySize, G64_SMEM);
        cudaFuncSetAttribute(gemm_ln_kernel,
                             cudaFuncAttributeMaxDynamicSharedMemorySize, LN_SMEM);
        cudaFuncSetAttribute(kv_tc_kernel,
                             cudaFuncAttributeMaxDynamicSharedMemorySize, KV_SMEM);
        cudaFuncSetAttribute(attn_tc_kernel,
                             cudaFuncAttributeMaxDynamicSharedMemorySize, GEMM_SMEM);
        attr_set = true;
    }

    // Combined bias [bq|bk|bv]
    cudaMemcpyAsync(bqkv,            bq, HS_ * sizeof(float), cudaMemcpyDeviceToDevice);
    cudaMemcpyAsync(bqkv + HS_,      bk, HS_ * sizeof(float), cudaMemcpyDeviceToDevice);
    cudaMemcpyAsync(bqkv + 2 * HS_,  bv, HS_ * sizeof(float), cudaMemcpyDeviceToDevice);

    dim3 t8(32, 8);
    // Weight transposes: Wq/Wk/Wv batched into one launch, then Wo/Wf1/Wf2
    transpose3_h_kernel<<<dim3(HS_/32, HS_/32, 3), t8>>>(Wq, Wk, Wv, WqkvT, HS_, HS_);
    transpose_h_kernel<<<dim3(HS_/32, HS_/32), t8>>>(Wo, WoT, HS_, HS_);
    transpose_h_kernel<<<dim3(FD_/32, HD_/32), t8>>>(Wf1, Wf1T, HD_, FD_);
    transpose_h_kernel<<<dim3(FD_/32, FD_/32), t8>>>(Wf2, Wf2T, FD_, FD_);

    f2h_kernel<<<(NROWS * HS_ / 4 + 255) / 256, 256>>>(
        (const float4*)X, (uint2*)Xh, NROWS * HS_ / 4);

    dim3 blk(256);

    // Fused QKV projection: [8192,2048] @ [6144,2048]^T -> q|k|v half buffers
    gemm_h_kernel<<<dim3(3 * HS_ / 128, NROWS / 128), blk, G64_SMEM>>>(
        Xh, WqkvT, bqkv, qkvh, NROWS, 3 * HS_, HS_, 0, 1, 1);

    // Fused feature gemm1 for q&k: M = 2*NTOK (q rows then k rows), K=128
    gemm_h_kernel<<<dim3(FD_ / 128, 2 * NTOK / 128), blk, G64_SMEM>>>(
        qh, Wf1T, bf1, tmph, 2 * NTOK, FD_, HD_, 1, 1, 0);

    // Fused gemm2 + LN for q&k -> head-major qfh / kfh (auto mask), 64-row CTAs
    gemm_ln_kernel<<<2 * NTOK / 64, blk, LN_SMEM>>>(
        tmph, Wf2T, bf2, ln_g, ln_b, mask, qfh, 2);

    // k_sum
    zero_ksum_kernel<<<BH_, FD_>>>(ksbuf);
    ksum_h_kernel<<<dim3(BH_, 8), 256>>>(kfh, ksbuf);

    // kv (8-way L split) + transposing reduce -> kvT half [bh][d][f]
    kv_tc_kernel<<<dim3(BH_, 8), blk, KV_SMEM>>>(kfh, vh, kvp);
    kv_reduce_t_kernel<<<dim3(FD_/32, HD_/32, BH_), 256>>>(kvp, kvT);

    // denom
    denom_kernel<<<NTOK / 8, 256>>>(qfh, ksbuf, den);

    // attn -> tok-major half
    attn_tc_kernel<<<dim3(BH_, L_ / 128), blk, GEMM_SMEM>>>(qfh, kvT, den, attnh);

    // output projection (fp32 to d_out) — G64_SMEM (was the R15 crash: GEMM_SMEM)
    gemm_h_kernel<<<dim3(HS_ / 128, NROWS / 128), blk, G64_SMEM>>>(
        attnh, WoT, bo, (float*)d_out, NROWS, HS_, HS_, 0, 0, 0);
}